// round 1
// baseline (speedup 1.0000x reference)
#include <cuda_runtime.h>
#include <math.h>
#include <stdint.h>

// ---------------- problem constants ----------------
constexpr int NODES = 50000;
constexpr int EDGES = 800000;
constexpr int E2    = EDGES + NODES;   // with self loops = 850000
constexpr int INCH  = 256;
constexpr int OUTC  = 64;
constexpr int HEADS = 4;
constexpr int HC    = HEADS * OUTC;    // 256
constexpr int NC    = 10;
constexpr float NEG = 0.2f;

// ---------------- scratch (static device allocations; no cudaMalloc) ----------------
__device__ float g_xl1[(size_t)NODES * HC];
__device__ float g_xr1[(size_t)NODES * HC];
__device__ float g_h1 [(size_t)NODES * HC];
__device__ float g_xl2[(size_t)NODES * OUTC];
__device__ float g_xr2[(size_t)NODES * OUTC];
__device__ float g_h2 [(size_t)NODES * OUTC];
__device__ float g_sc1[(size_t)E2 * HEADS];
__device__ float g_sc2[(size_t)E2];
__device__ int   g_m1 [NODES * HEADS];
__device__ float g_s1 [NODES * HEADS];
__device__ int   g_m2 [NODES];
__device__ float g_s2 [NODES];

// ---------------- helpers ----------------
// total-order mapping float <-> int so atomicMax(int) == max(float)
__device__ __forceinline__ int f2o(float f) {
    int i = __float_as_int(f);
    return (i >= 0) ? i : (i ^ 0x7FFFFFFF);
}
__device__ __forceinline__ float o2f(int i) {
    return __int_as_float((i >= 0) ? i : (i ^ 0x7FFFFFFF));
}
// encoded(-inf) = 0xFF800000 ^ 0x7FFFFFFF = 0x807FFFFF
#define MINF_ENC ((int)0x807FFFFFu)

// ---------------- init: zero accumulators, set max-trackers to -inf ----------------
__global__ void k_init() {
    int i = blockIdx.x * blockDim.x + threadIdx.x;
    if (i < NODES * HC)   g_h1[i] = 0.0f;
    if (i < NODES * OUTC) g_h2[i] = 0.0f;
    if (i < NODES * HEADS) { g_s1[i] = 0.0f; g_m1[i] = MINF_ENC; }
    if (i < NODES)         { g_s2[i] = 0.0f; g_m2[i] = MINF_ENC; }
}

// ---------------- fp32 SGEMM: C[M,Nc] = A[M,K] @ B[K,Nc] ----------------
// BM=BN=64, BK=16, 256 threads, 4x4 per thread. Nc multiple of 64, K multiple of 16.
__global__ void __launch_bounds__(256) sgemm64(const float* __restrict__ A,
                                               const float* __restrict__ B,
                                               float* __restrict__ C,
                                               int M, int Nc, int K) {
    __shared__ float As[16][64];
    __shared__ float Bs[16][64];
    int tid = threadIdx.x;
    int tx = tid & 15, ty = tid >> 4;
    int row0 = blockIdx.y * 64, col0 = blockIdx.x * 64;

    int arow = tid >> 2;          // 0..63
    int acol = (tid & 3) * 4;     // 0,4,8,12
    int brow = tid >> 4;          // 0..15
    int bcol = (tid & 15) * 4;    // 0..60

    float acc[4][4];
#pragma unroll
    for (int m = 0; m < 4; m++)
#pragma unroll
        for (int n = 0; n < 4; n++) acc[m][n] = 0.0f;

    for (int k0 = 0; k0 < K; k0 += 16) {
        float4 av = make_float4(0.f, 0.f, 0.f, 0.f);
        if (row0 + arow < M)
            av = *(const float4*)(A + (size_t)(row0 + arow) * K + k0 + acol);
        As[acol + 0][arow] = av.x;
        As[acol + 1][arow] = av.y;
        As[acol + 2][arow] = av.z;
        As[acol + 3][arow] = av.w;

        float4 bv = *(const float4*)(B + (size_t)(k0 + brow) * Nc + col0 + bcol);
        *(float4*)&Bs[brow][bcol] = bv;
        __syncthreads();

#pragma unroll
        for (int k = 0; k < 16; k++) {
            float4 ra = *(const float4*)&As[k][ty * 4];
            float4 rb = *(const float4*)&Bs[k][tx * 4];
            acc[0][0] += ra.x * rb.x; acc[0][1] += ra.x * rb.y; acc[0][2] += ra.x * rb.z; acc[0][3] += ra.x * rb.w;
            acc[1][0] += ra.y * rb.x; acc[1][1] += ra.y * rb.y; acc[1][2] += ra.y * rb.z; acc[1][3] += ra.y * rb.w;
            acc[2][0] += ra.z * rb.x; acc[2][1] += ra.z * rb.y; acc[2][2] += ra.z * rb.z; acc[2][3] += ra.z * rb.w;
            acc[3][0] += ra.w * rb.x; acc[3][1] += ra.w * rb.y; acc[3][2] += ra.w * rb.z; acc[3][3] += ra.w * rb.w;
        }
        __syncthreads();
    }
#pragma unroll
    for (int m = 0; m < 4; m++) {
        int r = row0 + ty * 4 + m;
        if (r < M) {
            float4 v = make_float4(acc[m][0], acc[m][1], acc[m][2], acc[m][3]);
            *(float4*)(C + (size_t)r * Nc + col0 + tx * 4) = v;
        }
    }
}

// ---------------- edge score: s[e,h] = sum_c lrelu(xl[src]+xr[dst]) * att[h,c]; atomicMax per dst ----------------
__global__ void k_score(const int* __restrict__ ei,
                        const float* __restrict__ xl, const float* __restrict__ xr,
                        const float* __restrict__ att,
                        float* __restrict__ sc, int* __restrict__ mmax, int Hh) {
    int t = blockIdx.x * blockDim.x + threadIdx.x;
    if (t >= E2 * Hh) return;
    int e = t / Hh, h = t - e * Hh;
    int src, dst;
    if (e < EDGES) { src = ei[e]; dst = ei[EDGES + e]; }
    else           { src = e - EDGES; dst = src; }
    int rowlen = Hh * OUTC;
    const float4* pl = (const float4*)(xl + (size_t)src * rowlen + h * OUTC);
    const float4* pr = (const float4*)(xr + (size_t)dst * rowlen + h * OUTC);
    const float4* pa = (const float4*)(att + h * OUTC);
    float s = 0.0f;
#pragma unroll
    for (int i = 0; i < OUTC / 4; i++) {
        float4 a = pl[i], b = pr[i], w = pa[i];
        float v0 = a.x + b.x, v1 = a.y + b.y, v2 = a.z + b.z, v3 = a.w + b.w;
        v0 = (v0 > 0.f) ? v0 : NEG * v0;
        v1 = (v1 > 0.f) ? v1 : NEG * v1;
        v2 = (v2 > 0.f) ? v2 : NEG * v2;
        v3 = (v3 > 0.f) ? v3 : NEG * v3;
        s += v0 * w.x + v1 * w.y + v2 * w.z + v3 * w.w;
    }
    sc[t] = s;
    atomicMax(&mmax[dst * Hh + h], f2o(s));
}

// ---------------- exp(score - max), accumulate segment sum ----------------
__global__ void k_exp(const int* __restrict__ ei, float* __restrict__ sc,
                      const int* __restrict__ mmax, float* __restrict__ ssum, int Hh) {
    int t = blockIdx.x * blockDim.x + threadIdx.x;
    if (t >= E2 * Hh) return;
    int e = t / Hh, h = t - e * Hh;
    int dst = (e < EDGES) ? ei[EDGES + e] : (e - EDGES);
    float m = o2f(mmax[dst * Hh + h]);
    float a = __expf(sc[t] - m);
    sc[t] = a;
    atomicAdd(&ssum[dst * Hh + h], a);
}

// ---------------- scatter: out[dst] += (a/s[dst]) * xl[src] ----------------
__global__ void k_scatter(const int* __restrict__ ei,
                          const float* __restrict__ xl,
                          const float* __restrict__ sc, const float* __restrict__ ssum,
                          float* __restrict__ outbuf, int Hh) {
    int t = blockIdx.x * blockDim.x + threadIdx.x;
    if (t >= E2 * Hh) return;
    int e = t / Hh, h = t - e * Hh;
    int src, dst;
    if (e < EDGES) { src = ei[e]; dst = ei[EDGES + e]; }
    else           { src = e - EDGES; dst = src; }
    float alpha = sc[t] / ssum[dst * Hh + h];
    int rowlen = Hh * OUTC;
    const float4* pl = (const float4*)(xl + (size_t)src * rowlen + h * OUTC);
    float* po = outbuf + (size_t)dst * rowlen + h * OUTC;
#pragma unroll
    for (int i = 0; i < OUTC / 4; i++) {
        float4 v = pl[i];
        atomicAdd(po + 4 * i + 0, alpha * v.x);
        atomicAdd(po + 4 * i + 1, alpha * v.y);
        atomicAdd(po + 4 * i + 2, alpha * v.z);
        atomicAdd(po + 4 * i + 3, alpha * v.w);
    }
}

// ---------------- relu(x + bias) in place ----------------
__global__ void k_relu_bias(float* __restrict__ buf, const float* __restrict__ bias,
                            int total, int rowlen) {
    int t = blockIdx.x * blockDim.x + threadIdx.x;
    if (t >= total) return;
    float v = buf[t] + bias[t % rowlen];
    buf[t] = (v > 0.f) ? v : 0.f;
}

// ---------------- final linear: out[n,c] = h2[n,:] @ Wlin[:,c] + blin[c] ----------------
__global__ void k_final(const float* __restrict__ h2, const float* __restrict__ Wlin,
                        const float* __restrict__ blin, float* __restrict__ out) {
    int t = blockIdx.x * blockDim.x + threadIdx.x;
    if (t >= NODES * NC) return;
    int n = t / NC, c = t - n * NC;
    float s = blin[c];
    const float* hr = h2 + (size_t)n * OUTC;
#pragma unroll
    for (int k = 0; k < OUTC; k++)
        s += hr[k] * Wlin[k * NC + c];
    out[t] = s;
}

// ---------------- launch ----------------
extern "C" void kernel_launch(void* const* d_in, const int* in_sizes, int n_in,
                              void* d_out, int out_size) {
    const float* x    = (const float*)d_in[0];
    const int*   ei   = (const int*)d_in[1];
    const float* Wl1  = (const float*)d_in[2];
    const float* Wr1  = (const float*)d_in[3];
    const float* att1 = (const float*)d_in[4];
    const float* b1   = (const float*)d_in[5];
    const float* Wl2  = (const float*)d_in[6];
    const float* Wr2  = (const float*)d_in[7];
    const float* att2 = (const float*)d_in[8];
    const float* b2   = (const float*)d_in[9];
    const float* Wlin = (const float*)d_in[10];
    const float* blin = (const float*)d_in[11];
    float* out = (float*)d_out;

    float *xl1, *xr1, *h1, *xl2, *xr2, *h2, *sc1, *sc2, *s1, *s2;
    int *m1, *m2;
    cudaGetSymbolAddress((void**)&xl1, g_xl1);
    cudaGetSymbolAddress((void**)&xr1, g_xr1);
    cudaGetSymbolAddress((void**)&h1,  g_h1);
    cudaGetSymbolAddress((void**)&xl2, g_xl2);
    cudaGetSymbolAddress((void**)&xr2, g_xr2);
    cudaGetSymbolAddress((void**)&h2,  g_h2);
    cudaGetSymbolAddress((void**)&sc1, g_sc1);
    cudaGetSymbolAddress((void**)&sc2, g_sc2);
    cudaGetSymbolAddress((void**)&s1,  g_s1);
    cudaGetSymbolAddress((void**)&s2,  g_s2);
    cudaGetSymbolAddress((void**)&m1,  g_m1);
    cudaGetSymbolAddress((void**)&m2,  g_m2);

    // init scratch
    {
        int total = NODES * HC;
        k_init<<<(total + 255) / 256, 256>>>();
    }

    // ---- layer 1 ----
    {
        dim3 g(HC / 64, (NODES + 63) / 64);
        sgemm64<<<g, 256>>>(x, Wl1, xl1, NODES, HC, INCH);
        sgemm64<<<g, 256>>>(x, Wr1, xr1, NODES, HC, INCH);
    }
    {
        int t = E2 * HEADS;
        int b = (t + 255) / 256;
        k_score  <<<b, 256>>>(ei, xl1, xr1, att1, sc1, m1, HEADS);
        k_exp    <<<b, 256>>>(ei, sc1, m1, s1, HEADS);
        k_scatter<<<b, 256>>>(ei, xl1, sc1, s1, h1, HEADS);
    }
    k_relu_bias<<<(NODES * HC + 255) / 256, 256>>>(h1, b1, NODES * HC, HC);

    // ---- layer 2 ----
    {
        dim3 g(OUTC / 64, (NODES + 63) / 64);
        sgemm64<<<g, 256>>>(h1, Wl2, xl2, NODES, OUTC, HC);
        sgemm64<<<g, 256>>>(h1, Wr2, xr2, NODES, OUTC, HC);
    }
    {
        int t = E2;
        int b = (t + 255) / 256;
        k_score  <<<b, 256>>>(ei, xl2, xr2, att2, sc2, m2, 1);
        k_exp    <<<b, 256>>>(ei, sc2, m2, s2, 1);
        k_scatter<<<b, 256>>>(ei, xl2, sc2, s2, h2, 1);
    }
    k_relu_bias<<<(NODES * OUTC + 255) / 256, 256>>>(h2, b2, NODES * OUTC, OUTC);

    // ---- classifier head ----
    k_final<<<(NODES * NC + 255) / 256, 256>>>(h2, Wlin, blin, out);
}

// round 2
// speedup vs baseline: 3.9344x; 3.9344x over previous
#include <cuda_runtime.h>
#include <math.h>

// ---------------- problem constants ----------------
constexpr int NODES = 50000;
constexpr int EDGES = 800000;
constexpr int E2    = EDGES + NODES;   // 850000
constexpr int INCH  = 256;
constexpr int OUTC  = 64;
constexpr int HC    = 256;             // 4 heads * 64
constexpr int NC    = 10;
constexpr float NEG = 0.2f;
constexpr int NB_SCAN = (NODES + 1023) / 1024;  // 49

// ---------------- scratch ----------------
__device__ float g_xl1[(size_t)NODES * HC];
__device__ float g_xr1[(size_t)NODES * HC];
__device__ float g_h1 [(size_t)NODES * HC];
__device__ float g_xl2[(size_t)NODES * OUTC];
__device__ float g_xr2[(size_t)NODES * OUTC];
__device__ float g_h2 [(size_t)NODES * OUTC];
__device__ int   g_deg[NODES];
__device__ int   g_scan[NODES];
__device__ int   g_rowptr[NODES + 1];
__device__ int   g_cursor[NODES];
__device__ int   g_csrc[E2];
__device__ int   g_bsum[64];
__device__ int   g_boff[64];

__device__ __forceinline__ float lrelu(float v) { return v > 0.f ? v : NEG * v; }

// ---------------- CSR build ----------------
__global__ void k_zero_deg() {
    int i = blockIdx.x * blockDim.x + threadIdx.x;
    if (i < NODES) g_deg[i] = 0;
}

__global__ void k_hist(const int* __restrict__ ei) {
    int e = blockIdx.x * blockDim.x + threadIdx.x;
    if (e >= E2) return;
    int dst = (e < EDGES) ? ei[EDGES + e] : (e - EDGES);
    atomicAdd(&g_deg[dst], 1);
}

__global__ void __launch_bounds__(1024) k_scan1() {
    __shared__ int sm[1024];
    int t = threadIdx.x;
    int i = blockIdx.x * 1024 + t;
    int v = (i < NODES) ? g_deg[i] : 0;
    sm[t] = v;
    __syncthreads();
#pragma unroll
    for (int d = 1; d < 1024; d <<= 1) {
        int x = (t >= d) ? sm[t - d] : 0;
        __syncthreads();
        sm[t] += x;
        __syncthreads();
    }
    if (i < NODES) g_scan[i] = sm[t];
    if (t == 1023) g_bsum[blockIdx.x] = sm[1023];
}

__global__ void k_scan2() {
    __shared__ int sm[64];
    int t = threadIdx.x;  // 64 threads, 1 block
    int v = (t < NB_SCAN) ? g_bsum[t] : 0;
    sm[t] = v;
    __syncthreads();
#pragma unroll
    for (int d = 1; d < 64; d <<= 1) {
        int x = (t >= d) ? sm[t - d] : 0;
        __syncthreads();
        sm[t] += x;
        __syncthreads();
    }
    g_boff[t] = sm[t] - v;  // exclusive
}

__global__ void __launch_bounds__(1024) k_scan3() {
    int t = threadIdx.x;
    int i = blockIdx.x * 1024 + t;
    if (i >= NODES) return;
    int incl = g_scan[i] + g_boff[blockIdx.x];
    int excl = incl - g_deg[i];
    g_rowptr[i] = excl;
    g_cursor[i] = excl;
    if (i == NODES - 1) g_rowptr[NODES] = incl;  // == E2
}

__global__ void k_fill(const int* __restrict__ ei) {
    int e = blockIdx.x * blockDim.x + threadIdx.x;
    if (e >= E2) return;
    int src, dst;
    if (e < EDGES) { src = ei[e]; dst = ei[EDGES + e]; }
    else           { src = e - EDGES; dst = src; }
    int pos = atomicAdd(&g_cursor[dst], 1);
    g_csrc[pos] = src;
}

// ---------------- fp32 SGEMM: 128x64 tile, BK=16, 256 threads, 8x4/thread ----------------
__global__ void __launch_bounds__(256) sgemm128(const float* __restrict__ A,
                                                const float* __restrict__ B,
                                                float* __restrict__ C,
                                                int M, int Nc, int K) {
    __shared__ float As[16][128];
    __shared__ float Bs[16][64];
    int tid = threadIdx.x;
    int tx = tid & 15, ty = tid >> 4;          // compute mapping
    int row0 = blockIdx.y * 128, col0 = blockIdx.x * 64;

    int arow = tid >> 1;                        // 0..127
    int acol = (tid & 1) * 8;                   // 0 or 8
    int brow = tid >> 4;                        // 0..15
    int bcol = (tid & 15) * 4;                  // 0..60

    float acc[8][4];
#pragma unroll
    for (int m = 0; m < 8; m++)
#pragma unroll
        for (int n = 0; n < 4; n++) acc[m][n] = 0.0f;

    for (int k0 = 0; k0 < K; k0 += 16) {
        float4 av0 = make_float4(0.f, 0.f, 0.f, 0.f);
        float4 av1 = make_float4(0.f, 0.f, 0.f, 0.f);
        if (row0 + arow < M) {
            const float* ap = A + (size_t)(row0 + arow) * K + k0 + acol;
            av0 = *(const float4*)ap;
            av1 = *(const float4*)(ap + 4);
        }
        As[acol + 0][arow] = av0.x; As[acol + 1][arow] = av0.y;
        As[acol + 2][arow] = av0.z; As[acol + 3][arow] = av0.w;
        As[acol + 4][arow] = av1.x; As[acol + 5][arow] = av1.y;
        As[acol + 6][arow] = av1.z; As[acol + 7][arow] = av1.w;

        *(float4*)&Bs[brow][bcol] = *(const float4*)(B + (size_t)(k0 + brow) * Nc + col0 + bcol);
        __syncthreads();

#pragma unroll
        for (int k = 0; k < 16; k++) {
            float ar[8];
            float4 r0 = *(const float4*)&As[k][ty * 8];
            float4 r1 = *(const float4*)&As[k][ty * 8 + 4];
            ar[0] = r0.x; ar[1] = r0.y; ar[2] = r0.z; ar[3] = r0.w;
            ar[4] = r1.x; ar[5] = r1.y; ar[6] = r1.z; ar[7] = r1.w;
            float4 bv = *(const float4*)&Bs[k][tx * 4];
#pragma unroll
            for (int m = 0; m < 8; m++) {
                acc[m][0] += ar[m] * bv.x;
                acc[m][1] += ar[m] * bv.y;
                acc[m][2] += ar[m] * bv.z;
                acc[m][3] += ar[m] * bv.w;
            }
        }
        __syncthreads();
    }
#pragma unroll
    for (int m = 0; m < 8; m++) {
        int r = row0 + ty * 8 + m;
        if (r < M) {
            float4 v = make_float4(acc[m][0], acc[m][1], acc[m][2], acc[m][3]);
            *(float4*)(C + (size_t)r * Nc + col0 + tx * 4) = v;
        }
    }
}

// ---------------- fused GATv2 aggregation, layer 1 (H=4, C=64) ----------------
// One warp per node; lane handles 8 channels of the 256-wide [H,C] row.
// Lanes 0-7 -> head 0, 8-15 -> head 1, etc. Online softmax in registers.
__global__ void __launch_bounds__(256) k_agg1(const int* __restrict__ rowptr,
                                              const int* __restrict__ csrc,
                                              const float* __restrict__ xl,
                                              const float* __restrict__ xr,
                                              const float* __restrict__ att,
                                              const float* __restrict__ bias,
                                              float* __restrict__ out) {
    int warp = (blockIdx.x * blockDim.x + threadIdx.x) >> 5;
    int lane = threadIdx.x & 31;
    if (warp >= NODES) return;
    int n = warp;
    int off = lane * 8;

    const float4* pr = (const float4*)(xr + (size_t)n * HC + off);
    float4 r0 = pr[0], r1 = pr[1];
    const float4* pa = (const float4*)(att + off);
    float4 a0 = pa[0], a1 = pa[1];

    float m = -INFINITY, s = 0.f;
    float acc[8] = {0.f, 0.f, 0.f, 0.f, 0.f, 0.f, 0.f, 0.f};

    int b = rowptr[n], e = rowptr[n + 1];
    for (int kb = b; kb < e; kb += 32) {
        int idx = kb + lane;
        int mysrc = (idx < e) ? csrc[idx] : 0;
        int cnt = min(32, e - kb);
        for (int j = 0; j < cnt; j++) {
            int src = __shfl_sync(0xffffffffu, mysrc, j);
            const float4* pl = (const float4*)(xl + (size_t)src * HC + off);
            float4 v0 = pl[0], v1 = pl[1];
            float p = lrelu(v0.x + r0.x) * a0.x + lrelu(v0.y + r0.y) * a0.y
                    + lrelu(v0.z + r0.z) * a0.z + lrelu(v0.w + r0.w) * a0.w
                    + lrelu(v1.x + r1.x) * a1.x + lrelu(v1.y + r1.y) * a1.y
                    + lrelu(v1.z + r1.z) * a1.z + lrelu(v1.w + r1.w) * a1.w;
            // reduce over the 8-lane subgroup (one head)
            p += __shfl_xor_sync(0xffffffffu, p, 1);
            p += __shfl_xor_sync(0xffffffffu, p, 2);
            p += __shfl_xor_sync(0xffffffffu, p, 4);
            // online softmax update
            float w;
            if (p > m) {
                float f = __expf(m - p);   // m=-inf -> f=0
                s *= f;
#pragma unroll
                for (int q = 0; q < 8; q++) acc[q] *= f;
                m = p;
                w = 1.0f;
            } else {
                w = __expf(p - m);
            }
            s += w;
            acc[0] += w * v0.x; acc[1] += w * v0.y; acc[2] += w * v0.z; acc[3] += w * v0.w;
            acc[4] += w * v1.x; acc[5] += w * v1.y; acc[6] += w * v1.z; acc[7] += w * v1.w;
        }
    }
    float inv = 1.0f / s;
    const float4* pb = (const float4*)(bias + off);
    float4 b0 = pb[0], b1 = pb[1];
    float4 o0, o1;
    o0.x = fmaxf(acc[0] * inv + b0.x, 0.f);
    o0.y = fmaxf(acc[1] * inv + b0.y, 0.f);
    o0.z = fmaxf(acc[2] * inv + b0.z, 0.f);
    o0.w = fmaxf(acc[3] * inv + b0.w, 0.f);
    o1.x = fmaxf(acc[4] * inv + b1.x, 0.f);
    o1.y = fmaxf(acc[5] * inv + b1.y, 0.f);
    o1.z = fmaxf(acc[6] * inv + b1.z, 0.f);
    o1.w = fmaxf(acc[7] * inv + b1.w, 0.f);
    float4* po = (float4*)(out + (size_t)n * HC + off);
    po[0] = o0; po[1] = o1;
}

// ---------------- fused GATv2 aggregation, layer 2 (H=1, C=64) ----------------
// One warp per node; lane handles 2 channels.
__global__ void __launch_bounds__(256) k_agg2(const int* __restrict__ rowptr,
                                              const int* __restrict__ csrc,
                                              const float* __restrict__ xl,
                                              const float* __restrict__ xr,
                                              const float* __restrict__ att,
                                              const float* __restrict__ bias,
                                              float* __restrict__ out) {
    int warp = (blockIdx.x * blockDim.x + threadIdx.x) >> 5;
    int lane = threadIdx.x & 31;
    if (warp >= NODES) return;
    int n = warp;
    int off = lane * 2;

    float2 r = *(const float2*)(xr + (size_t)n * OUTC + off);
    float2 a = *(const float2*)(att + off);

    float m = -INFINITY, s = 0.f;
    float acc0 = 0.f, acc1 = 0.f;

    int b = rowptr[n], e = rowptr[n + 1];
    for (int kb = b; kb < e; kb += 32) {
        int idx = kb + lane;
        int mysrc = (idx < e) ? csrc[idx] : 0;
        int cnt = min(32, e - kb);
        for (int j = 0; j < cnt; j++) {
            int src = __shfl_sync(0xffffffffu, mysrc, j);
            float2 v = *(const float2*)(xl + (size_t)src * OUTC + off);
            float p = lrelu(v.x + r.x) * a.x + lrelu(v.y + r.y) * a.y;
            p += __shfl_xor_sync(0xffffffffu, p, 1);
            p += __shfl_xor_sync(0xffffffffu, p, 2);
            p += __shfl_xor_sync(0xffffffffu, p, 4);
            p += __shfl_xor_sync(0xffffffffu, p, 8);
            p += __shfl_xor_sync(0xffffffffu, p, 16);
            float w;
            if (p > m) {
                float f = __expf(m - p);
                s *= f; acc0 *= f; acc1 *= f;
                m = p; w = 1.0f;
            } else {
                w = __expf(p - m);
            }
            s += w;
            acc0 += w * v.x;
            acc1 += w * v.y;
        }
    }
    float inv = 1.0f / s;
    float2 bb = *(const float2*)(bias + off);
    float2 o;
    o.x = fmaxf(acc0 * inv + bb.x, 0.f);
    o.y = fmaxf(acc1 * inv + bb.y, 0.f);
    *(float2*)(out + (size_t)n * OUTC + off) = o;
}

// ---------------- final linear: out[n,c] = h2[n,:] @ Wlin[:,c] + blin[c] ----------------
__global__ void __launch_bounds__(256) k_final(const float* __restrict__ h2,
                                               const float* __restrict__ Wlin,
                                               const float* __restrict__ blin,
                                               float* __restrict__ out) {
    __shared__ float sW[OUTC * NC];
    __shared__ float sb[NC];
    for (int i = threadIdx.x; i < OUTC * NC; i += blockDim.x) sW[i] = Wlin[i];
    if (threadIdx.x < NC) sb[threadIdx.x] = blin[threadIdx.x];
    __syncthreads();
    int t = blockIdx.x * blockDim.x + threadIdx.x;
    if (t >= NODES * NC) return;
    int n = t / NC, c = t - n * NC;
    float sacc = sb[c];
    const float* hr = h2 + (size_t)n * OUTC;
#pragma unroll
    for (int k = 0; k < OUTC; k++)
        sacc += hr[k] * sW[k * NC + c];
    out[t] = sacc;
}

// ---------------- launch ----------------
extern "C" void kernel_launch(void* const* d_in, const int* in_sizes, int n_in,
                              void* d_out, int out_size) {
    const float* x    = (const float*)d_in[0];
    const int*   ei   = (const int*)d_in[1];
    const float* Wl1  = (const float*)d_in[2];
    const float* Wr1  = (const float*)d_in[3];
    const float* att1 = (const float*)d_in[4];
    const float* b1   = (const float*)d_in[5];
    const float* Wl2  = (const float*)d_in[6];
    const float* Wr2  = (const float*)d_in[7];
    const float* att2 = (const float*)d_in[8];
    const float* b2   = (const float*)d_in[9];
    const float* Wlin = (const float*)d_in[10];
    const float* blin = (const float*)d_in[11];
    float* out = (float*)d_out;

    float *xl1, *xr1, *h1, *xl2, *xr2, *h2;
    int *rowptr, *csrc;
    cudaGetSymbolAddress((void**)&xl1, g_xl1);
    cudaGetSymbolAddress((void**)&xr1, g_xr1);
    cudaGetSymbolAddress((void**)&h1,  g_h1);
    cudaGetSymbolAddress((void**)&xl2, g_xl2);
    cudaGetSymbolAddress((void**)&xr2, g_xr2);
    cudaGetSymbolAddress((void**)&h2,  g_h2);
    cudaGetSymbolAddress((void**)&rowptr, g_rowptr);
    cudaGetSymbolAddress((void**)&csrc,   g_csrc);

    int ethreads = (E2 + 255) / 256;

    // ---- CSR build ----
    k_zero_deg<<<(NODES + 255) / 256, 256>>>();
    k_hist<<<ethreads, 256>>>(ei);
    k_scan1<<<NB_SCAN, 1024>>>();
    k_scan2<<<1, 64>>>();
    k_scan3<<<NB_SCAN, 1024>>>();
    k_fill<<<ethreads, 256>>>(ei);

    // ---- layer 1 GEMMs ----
    {
        dim3 g(HC / 64, (NODES + 127) / 128);
        sgemm128<<<g, 256>>>(x, Wl1, xl1, NODES, HC, INCH);
        sgemm128<<<g, 256>>>(x, Wr1, xr1, NODES, HC, INCH);
    }
    // ---- layer 1 aggregation (fused score/softmax/scatter/bias/relu) ----
    k_agg1<<<(NODES + 7) / 8, 256>>>(rowptr, csrc, xl1, xr1, att1, b1, h1);

    // ---- layer 2 GEMMs ----
    {
        dim3 g(OUTC / 64, (NODES + 127) / 128);
        sgemm128<<<g, 256>>>(h1, Wl2, xl2, NODES, OUTC, HC);
        sgemm128<<<g, 256>>>(h1, Wr2, xr2, NODES, OUTC, HC);
    }
    // ---- layer 2 aggregation ----
    k_agg2<<<(NODES + 7) / 8, 256>>>(rowptr, csrc, xl2, xr2, att2, b2, h2);

    // ---- classifier head ----
    k_final<<<(NODES * NC + 255) / 256, 256>>>(h2, Wlin, blin, out);
}

// round 4
// speedup vs baseline: 6.2200x; 1.5809x over previous
#include <cuda_runtime.h>
#include <cuda_bf16.h>
#include <math.h>
#include <stdint.h>

// ---------------- problem constants ----------------
constexpr int NODES = 50000;
constexpr int EDGES = 800000;
constexpr int E2    = EDGES + NODES;   // 850000
constexpr int INCH  = 256;
constexpr int OUTC  = 64;
constexpr int HC    = 256;             // 4 heads * 64
constexpr int NC    = 10;
constexpr float NEG = 0.2f;
constexpr int NB_SCAN = (NODES + 1023) / 1024;  // 49

// ---------------- scratch ----------------
__device__ float g_xl1[(size_t)NODES * HC];
__device__ float g_xr1[(size_t)NODES * HC];
__device__ float g_h1 [(size_t)NODES * HC];
__device__ float g_xl2[(size_t)NODES * OUTC];
__device__ float g_xr2[(size_t)NODES * OUTC];
__device__ float g_h2 [(size_t)NODES * OUTC];
__device__ int   g_deg[NODES];
__device__ int   g_scan[NODES];
__device__ int   g_rowptr[NODES + 1];
__device__ int   g_cursor[NODES];
__device__ int   g_csrc[E2];
__device__ int   g_bsum[64];
__device__ int   g_boff[64];
// transposed + bf16 hi/lo split weights: layer1 [512][256], layer2 [128][256]
__device__ __nv_bfloat16 g_bt1_hi[512 * 256];
__device__ __nv_bfloat16 g_bt1_lo[512 * 256];
__device__ __nv_bfloat16 g_bt2_hi[128 * 256];
__device__ __nv_bfloat16 g_bt2_lo[128 * 256];

__device__ __forceinline__ float lrelu(float v) { return v > 0.f ? v : NEG * v; }

__device__ __forceinline__ uint32_t smem_u32(const void* p) {
    uint32_t a;
    asm("{ .reg .u64 t; cvta.to.shared.u64 t, %1; cvt.u32.u64 %0, t; }" : "=r"(a) : "l"(p));
    return a;
}

__device__ __forceinline__ void ldsm_x4(uint32_t* r, uint32_t addr) {
    asm volatile("ldmatrix.sync.aligned.m8n8.x4.shared.b16 {%0,%1,%2,%3}, [%4];"
                 : "=r"(r[0]), "=r"(r[1]), "=r"(r[2]), "=r"(r[3]) : "r"(addr));
}
__device__ __forceinline__ void ldsm_x2(uint32_t* r, uint32_t addr) {
    asm volatile("ldmatrix.sync.aligned.m8n8.x2.shared.b16 {%0,%1}, [%2];"
                 : "=r"(r[0]), "=r"(r[1]) : "r"(addr));
}
__device__ __forceinline__ void mma_bf16(float* c, const uint32_t* a, const uint32_t* b) {
    asm volatile("mma.sync.aligned.m16n8k16.row.col.f32.bf16.bf16.f32 "
                 "{%0,%1,%2,%3}, {%4,%5,%6,%7}, {%8,%9}, {%0,%1,%2,%3};"
                 : "+f"(c[0]), "+f"(c[1]), "+f"(c[2]), "+f"(c[3])
                 : "r"(a[0]), "r"(a[1]), "r"(a[2]), "r"(a[3]), "r"(b[0]), "r"(b[1]));
}

// ---------------- weight prep: transpose + bf16 hi/lo split ----------------
// bt layout [(mat*N + n)][k]; W0/W1 are [K][N] row-major. K=256.
__global__ void k_prep_B(const float* __restrict__ W0, const float* __restrict__ W1,
                         __nv_bfloat16* __restrict__ bt_hi, __nv_bfloat16* __restrict__ bt_lo,
                         int N, int K) {
    int t = blockIdx.x * blockDim.x + threadIdx.x;
    int total = 2 * N * K;
    if (t >= total) return;
    int mat = t / (N * K);
    int r = t - mat * (N * K);
    int n = r / K, k = r - n * K;
    const float* W = mat ? W1 : W0;
    float w = W[k * N + n];
    __nv_bfloat16 hi = __float2bfloat16_rn(w);
    bt_hi[t] = hi;
    bt_lo[t] = __float2bfloat16_rn(w - __bfloat162float(hi));
}

// ---------------- bf16x3 tensor-core GEMM (mma.sync) ----------------
// C_cat[M, N_TOTAL] = A[M,256] @ Bt^T, Bt=[N_TOTAL][256] pre-split hi/lo.
// Columns [0,NBM) -> C0, [NBM,2*NBM) -> C1. CTA tile 128x128, 8 warps (2x4).
template <int NBM>
__global__ void __launch_bounds__(256, 1) gemm_mma(const float* __restrict__ A,
                                                   const __nv_bfloat16* __restrict__ Bh,
                                                   const __nv_bfloat16* __restrict__ Bl,
                                                   float* __restrict__ C0,
                                                   float* __restrict__ C1,
                                                   int M) {
    constexpr int K = 256;
    constexpr int LDS = 40;             // padded row length (elements) -> 80B, conflict-free
    __shared__ __nv_bfloat16 sAh[128 * LDS];
    __shared__ __nv_bfloat16 sAl[128 * LDS];
    __shared__ __nv_bfloat16 sBh[128 * LDS];
    __shared__ __nv_bfloat16 sBl[128 * LDS];

    int tid = threadIdx.x;
    int lane = tid & 31;
    int wid = tid >> 5;
    int warpM = wid >> 2;               // 0..1
    int warpN = wid & 3;                // 0..3
    int m0 = blockIdx.y * 128;
    int n0 = blockIdx.x * 128;

    uint32_t bAh = smem_u32(sAh), bAl = smem_u32(sAl);
    uint32_t bBh = smem_u32(sBh), bBl = smem_u32(sBl);

    // prefetch registers
    float4 apf[4];
    int4 bhpf[2], blpf[2];

    auto gload = [&](int kb) {
#pragma unroll
        for (int i = 0; i < 4; i++) {
            int u = tid + 256 * i;      // 0..1023
            int row = u >> 3, c4 = u & 7;
            apf[i] = make_float4(0.f, 0.f, 0.f, 0.f);
            if (m0 + row < M)
                apf[i] = *(const float4*)(A + (size_t)(m0 + row) * K + kb * 32 + c4 * 4);
        }
#pragma unroll
        for (int i = 0; i < 2; i++) {
            int u = tid + 256 * i;      // 0..511
            int row = u >> 2, c = u & 3;
            size_t g = (size_t)(n0 + row) * K + kb * 32 + c * 8;
            bhpf[i] = *(const int4*)(Bh + g);
            blpf[i] = *(const int4*)(Bl + g);
        }
    };

    auto sstore = [&]() {
#pragma unroll
        for (int i = 0; i < 4; i++) {
            int u = tid + 256 * i;
            int row = u >> 3, c4 = u & 7;
            float4 v = apf[i];
            __nv_bfloat162 h0, h1, l0, l1;
            h0.x = __float2bfloat16_rn(v.x);
            h0.y = __float2bfloat16_rn(v.y);
            h1.x = __float2bfloat16_rn(v.z);
            h1.y = __float2bfloat16_rn(v.w);
            l0.x = __float2bfloat16_rn(v.x - __bfloat162float(h0.x));
            l0.y = __float2bfloat16_rn(v.y - __bfloat162float(h0.y));
            l1.x = __float2bfloat16_rn(v.z - __bfloat162float(h1.x));
            l1.y = __float2bfloat16_rn(v.w - __bfloat162float(h1.y));
            int e = row * LDS + c4 * 4;
            *(__nv_bfloat162*)(sAh + e)     = h0;
            *(__nv_bfloat162*)(sAh + e + 2) = h1;
            *(__nv_bfloat162*)(sAl + e)     = l0;
            *(__nv_bfloat162*)(sAl + e + 2) = l1;
        }
#pragma unroll
        for (int i = 0; i < 2; i++) {
            int u = tid + 256 * i;
            int row = u >> 2, c = u & 3;
            int e = row * LDS + c * 8;
            *(int4*)(sBh + e) = bhpf[i];
            *(int4*)(sBl + e) = blpf[i];
        }
    };

    float acc[4][4][4];
#pragma unroll
    for (int f = 0; f < 4; f++)
#pragma unroll
        for (int g = 0; g < 4; g++)
#pragma unroll
            for (int q = 0; q < 4; q++) acc[f][g][q] = 0.f;

    // ldmatrix per-thread smem addresses (element offsets precomputed per kk)
    int arow = warpM * 64 + (lane & 15);
    int akc  = (lane >> 4) << 3;               // 0 or 8
    int brow = warpN * 32 + (lane & 7);
    int bkc  = ((lane >> 3) & 1) << 3;         // 0 or 8 (lanes 16+ replicate)

    gload(0);
    for (int kb = 0; kb < 8; kb++) {
        sstore();
        __syncthreads();
        if (kb < 7) gload(kb + 1);

#pragma unroll
        for (int kk = 0; kk < 2; kk++) {
            uint32_t aoff = (uint32_t)((arow * LDS + kk * 16 + akc) * 2);
            uint32_t boff = (uint32_t)((brow * LDS + kk * 16 + bkc) * 2);

            uint32_t ah[4][4], bh[4][2];
#pragma unroll
            for (int f = 0; f < 4; f++)
                ldsm_x4(ah[f], bAh + aoff + (uint32_t)(f * 16 * LDS * 2));
#pragma unroll
            for (int g = 0; g < 4; g++)
                ldsm_x2(bh[g], bBh + boff + (uint32_t)(g * 8 * LDS * 2));
#pragma unroll
            for (int f = 0; f < 4; f++)
#pragma unroll
                for (int g = 0; g < 4; g++)
                    mma_bf16(acc[f][g], ah[f], bh[g]);

            uint32_t bl[4][2];
#pragma unroll
            for (int g = 0; g < 4; g++)
                ldsm_x2(bl[g], bBl + boff + (uint32_t)(g * 8 * LDS * 2));
#pragma unroll
            for (int f = 0; f < 4; f++)
#pragma unroll
                for (int g = 0; g < 4; g++)
                    mma_bf16(acc[f][g], ah[f], bl[g]);

            uint32_t al[4][4];
#pragma unroll
            for (int f = 0; f < 4; f++)
                ldsm_x4(al[f], bAl + aoff + (uint32_t)(f * 16 * LDS * 2));
#pragma unroll
            for (int f = 0; f < 4; f++)
#pragma unroll
                for (int g = 0; g < 4; g++)
                    mma_bf16(acc[f][g], al[f], bh[g]);
        }
        __syncthreads();
    }

    // ---- epilogue ----
#pragma unroll
    for (int f = 0; f < 4; f++) {
#pragma unroll
        for (int g = 0; g < 4; g++) {
            int row = m0 + warpM * 64 + f * 16 + (lane >> 2);
            int col = n0 + warpN * 32 + g * 8 + (lane & 3) * 2;
            int mat = col / NBM;
            int cc = col - mat * NBM;
            float* Cp = mat ? C1 : C0;
            if (row < M) {
                float2 v = make_float2(acc[f][g][0], acc[f][g][1]);
                *(float2*)(Cp + (size_t)row * NBM + cc) = v;
            }
            if (row + 8 < M) {
                float2 v = make_float2(acc[f][g][2], acc[f][g][3]);
                *(float2*)(Cp + (size_t)(row + 8) * NBM + cc) = v;
            }
        }
    }
}

// ---------------- CSR build ----------------
__global__ void k_zero_deg() {
    int i = blockIdx.x * blockDim.x + threadIdx.x;
    if (i < NODES) g_deg[i] = 0;
}

__global__ void k_hist(const int* __restrict__ ei) {
    int e = blockIdx.x * blockDim.x + threadIdx.x;
    if (e >= E2) return;
    int dst = (e < EDGES) ? ei[EDGES + e] : (e - EDGES);
    atomicAdd(&g_deg[dst], 1);
}

__global__ void __launch_bounds__(1024) k_scan1() {
    __shared__ int sm[1024];
    int t = threadIdx.x;
    int i = blockIdx.x * 1024 + t;
    int v = (i < NODES) ? g_deg[i] : 0;
    sm[t] = v;
    __syncthreads();
#pragma unroll
    for (int d = 1; d < 1024; d <<= 1) {
        int x = (t >= d) ? sm[t - d] : 0;
        __syncthreads();
        sm[t] += x;
        __syncthreads();
    }
    if (i < NODES) g_scan[i] = sm[t];
    if (t == 1023) g_bsum[blockIdx.x] = sm[1023];
}

__global__ void k_scan2() {
    __shared__ int sm[64];
    int t = threadIdx.x;
    int v = (t < NB_SCAN) ? g_bsum[t] : 0;
    sm[t] = v;
    __syncthreads();
#pragma unroll
    for (int d = 1; d < 64; d <<= 1) {
        int x = (t >= d) ? sm[t - d] : 0;
        __syncthreads();
        sm[t] += x;
        __syncthreads();
    }
    g_boff[t] = sm[t] - v;
}

__global__ void __launch_bounds__(1024) k_scan3() {
    int t = threadIdx.x;
    int i = blockIdx.x * 1024 + t;
    if (i >= NODES) return;
    int incl = g_scan[i] + g_boff[blockIdx.x];
    int excl = incl - g_deg[i];
    g_rowptr[i] = excl;
    g_cursor[i] = excl;
    if (i == NODES - 1) g_rowptr[NODES] = incl;
}

__global__ void k_fill(const int* __restrict__ ei) {
    int e = blockIdx.x * blockDim.x + threadIdx.x;
    if (e >= E2) return;
    int src, dst;
    if (e < EDGES) { src = ei[e]; dst = ei[EDGES + e]; }
    else           { src = e - EDGES; dst = src; }
    int pos = atomicAdd(&g_cursor[dst], 1);
    g_csrc[pos] = src;
}

// ---------------- fused GATv2 aggregation, layer 1 (H=4, C=64) ----------------
__global__ void __launch_bounds__(256) k_agg1(const int* __restrict__ rowptr,
                                              const int* __restrict__ csrc,
                                              const float* __restrict__ xl,
                                              const float* __restrict__ xr,
                                              const float* __restrict__ att,
                                              const float* __restrict__ bias,
                                              float* __restrict__ out) {
    int warp = (blockIdx.x * blockDim.x + threadIdx.x) >> 5;
    int lane = threadIdx.x & 31;
    if (warp >= NODES) return;
    int n = warp;
    int off = lane * 8;

    const float4* pr = (const float4*)(xr + (size_t)n * HC + off);
    float4 r0 = pr[0], r1 = pr[1];
    const float4* pa = (const float4*)(att + off);
    float4 a0 = pa[0], a1 = pa[1];

    float m = -INFINITY, s = 0.f;
    float acc[8] = {0.f, 0.f, 0.f, 0.f, 0.f, 0.f, 0.f, 0.f};

    int b = rowptr[n], e = rowptr[n + 1];
    for (int kb = b; kb < e; kb += 32) {
        int idx = kb + lane;
        int mysrc = (idx < e) ? csrc[idx] : 0;
        int cnt = min(32, e - kb);
        for (int j = 0; j < cnt; j++) {
            int src = __shfl_sync(0xffffffffu, mysrc, j);
            const float4* pl = (const float4*)(xl + (size_t)src * HC + off);
            float4 v0 = pl[0], v1 = pl[1];
            float p = lrelu(v0.x + r0.x) * a0.x + lrelu(v0.y + r0.y) * a0.y
                    + lrelu(v0.z + r0.z) * a0.z + lrelu(v0.w + r0.w) * a0.w
                    + lrelu(v1.x + r1.x) * a1.x + lrelu(v1.y + r1.y) * a1.y
                    + lrelu(v1.z + r1.z) * a1.z + lrelu(v1.w + r1.w) * a1.w;
            p += __shfl_xor_sync(0xffffffffu, p, 1);
            p += __shfl_xor_sync(0xffffffffu, p, 2);
            p += __shfl_xor_sync(0xffffffffu, p, 4);
            float w;
            if (p > m) {
                float f = __expf(m - p);
                s *= f;
#pragma unroll
                for (int q = 0; q < 8; q++) acc[q] *= f;
                m = p;
                w = 1.0f;
            } else {
                w = __expf(p - m);
            }
            s += w;
            acc[0] += w * v0.x; acc[1] += w * v0.y; acc[2] += w * v0.z; acc[3] += w * v0.w;
            acc[4] += w * v1.x; acc[5] += w * v1.y; acc[6] += w * v1.z; acc[7] += w * v1.w;
        }
    }
    float inv = 1.0f / s;
    const float4* pb = (const float4*)(bias + off);
    float4 b0 = pb[0], b1 = pb[1];
    float4 o0, o1;
    o0.x = fmaxf(acc[0] * inv + b0.x, 0.f);
    o0.y = fmaxf(acc[1] * inv + b0.y, 0.f);
    o0.z = fmaxf(acc[2] * inv + b0.z, 0.f);
    o0.w = fmaxf(acc[3] * inv + b0.w, 0.f);
    o1.x = fmaxf(acc[4] * inv + b1.x, 0.f);
    o1.y = fmaxf(acc[5] * inv + b1.y, 0.f);
    o1.z = fmaxf(acc[6] * inv + b1.z, 0.f);
    o1.w = fmaxf(acc[7] * inv + b1.w, 0.f);
    float4* po = (float4*)(out + (size_t)n * HC + off);
    po[0] = o0; po[1] = o1;
}

// ---------------- fused GATv2 aggregation, layer 2 (H=1, C=64) ----------------
__global__ void __launch_bounds__(256) k_agg2(const int* __restrict__ rowptr,
                                              const int* __restrict__ csrc,
                                              const float* __restrict__ xl,
                                              const float* __restrict__ xr,
                                              const float* __restrict__ att,
                                              const float* __restrict__ bias,
                                              float* __restrict__ out) {
    int warp = (blockIdx.x * blockDim.x + threadIdx.x) >> 5;
    int lane = threadIdx.x & 31;
    if (warp >= NODES) return;
    int n = warp;
    int off = lane * 2;

    float2 r = *(const float2*)(xr + (size_t)n * OUTC + off);
    float2 a = *(const float2*)(att + off);

    float m = -INFINITY, s = 0.f;
    float acc0 = 0.f, acc1 = 0.f;

    int b = rowptr[n], e = rowptr[n + 1];
    for (int kb = b; kb < e; kb += 32) {
        int idx = kb + lane;
        int mysrc = (idx < e) ? csrc[idx] : 0;
        int cnt = min(32, e - kb);
        for (int j = 0; j < cnt; j++) {
            int src = __shfl_sync(0xffffffffu, mysrc, j);
            float2 v = *(const float2*)(xl + (size_t)src * OUTC + off);
            float p = lrelu(v.x + r.x) * a.x + lrelu(v.y + r.y) * a.y;
            p += __shfl_xor_sync(0xffffffffu, p, 1);
            p += __shfl_xor_sync(0xffffffffu, p, 2);
            p += __shfl_xor_sync(0xffffffffu, p, 4);
            p += __shfl_xor_sync(0xffffffffu, p, 8);
            p += __shfl_xor_sync(0xffffffffu, p, 16);
            float w;
            if (p > m) {
                float f = __expf(m - p);
                s *= f; acc0 *= f; acc1 *= f;
                m = p; w = 1.0f;
            } else {
                w = __expf(p - m);
            }
            s += w;
            acc0 += w * v.x;
            acc1 += w * v.y;
        }
    }
    float inv = 1.0f / s;
    float2 bb = *(const float2*)(bias + off);
    float2 o;
    o.x = fmaxf(acc0 * inv + bb.x, 0.f);
    o.y = fmaxf(acc1 * inv + bb.y, 0.f);
    *(float2*)(out + (size_t)n * OUTC + off) = o;
}

// ---------------- final linear ----------------
__global__ void __launch_bounds__(256) k_final(const float* __restrict__ h2,
                                               const float* __restrict__ Wlin,
                                               const float* __restrict__ blin,
                                               float* __restrict__ out) {
    __shared__ float sW[OUTC * NC];
    __shared__ float sb[NC];
    for (int i = threadIdx.x; i < OUTC * NC; i += blockDim.x) sW[i] = Wlin[i];
    if (threadIdx.x < NC) sb[threadIdx.x] = blin[threadIdx.x];
    __syncthreads();
    int t = blockIdx.x * blockDim.x + threadIdx.x;
    if (t >= NODES * NC) return;
    int n = t / NC, c = t - n * NC;
    float sacc = sb[c];
    const float* hr = h2 + (size_t)n * OUTC;
#pragma unroll
    for (int k = 0; k < OUTC; k++)
        sacc += hr[k] * sW[k * NC + c];
    out[t] = sacc;
}

// ---------------- launch ----------------
extern "C" void kernel_launch(void* const* d_in, const int* in_sizes, int n_in,
                              void* d_out, int out_size) {
    const float* x    = (const float*)d_in[0];
    const int*   ei   = (const int*)d_in[1];
    const float* Wl1  = (const float*)d_in[2];
    const float* Wr1  = (const float*)d_in[3];
    const float* att1 = (const float*)d_in[4];
    const float* b1   = (const float*)d_in[5];
    const float* Wl2  = (const float*)d_in[6];
    const float* Wr2  = (const float*)d_in[7];
    const float* att2 = (const float*)d_in[8];
    const float* b2   = (const float*)d_in[9];
    const float* Wlin = (const float*)d_in[10];
    const float* blin = (const float*)d_in[11];
    float* out = (float*)d_out;

    float *xl1, *xr1, *h1, *xl2, *xr2, *h2;
    __nv_bfloat16 *bt1h, *bt1l, *bt2h, *bt2l;
    int *rowptr, *csrc;
    cudaGetSymbolAddress((void**)&xl1, g_xl1);
    cudaGetSymbolAddress((void**)&xr1, g_xr1);
    cudaGetSymbolAddress((void**)&h1,  g_h1);
    cudaGetSymbolAddress((void**)&xl2, g_xl2);
    cudaGetSymbolAddress((void**)&xr2, g_xr2);
    cudaGetSymbolAddress((void**)&h2,  g_h2);
    cudaGetSymbolAddress((void**)&rowptr, g_rowptr);
    cudaGetSymbolAddress((void**)&csrc,   g_csrc);
    cudaGetSymbolAddress((void**)&bt1h, g_bt1_hi);
    cudaGetSymbolAddress((void**)&bt1l, g_bt1_lo);
    cudaGetSymbolAddress((void**)&bt2h, g_bt2_hi);
    cudaGetSymbolAddress((void**)&bt2l, g_bt2_lo);

    int ethreads = (E2 + 255) / 256;
    int mrows = (NODES + 127) / 128;   // 391

    // ---- weight prep (transpose + bf16 hi/lo split) ----
    k_prep_B<<<(2 * 256 * 256 + 255) / 256, 256>>>(Wl1, Wr1, bt1h, bt1l, 256, 256);
    k_prep_B<<<(2 * 64 * 256 + 255) / 256, 256>>>(Wl2, Wr2, bt2h, bt2l, 64, 256);

    // ---- CSR build ----
    k_zero_deg<<<(NODES + 255) / 256, 256>>>();
    k_hist<<<ethreads, 256>>>(ei);
    k_scan1<<<NB_SCAN, 1024>>>();
    k_scan2<<<1, 64>>>();
    k_scan3<<<NB_SCAN, 1024>>>();
    k_fill<<<ethreads, 256>>>(ei);

    // ---- layer 1: fused GEMM pair (tensor cores, bf16x3) + aggregation ----
    gemm_mma<256><<<dim3(4, mrows), 256>>>(x, bt1h, bt1l, xl1, xr1, NODES);
    k_agg1<<<(NODES + 7) / 8, 256>>>(rowptr, csrc, xl1, xr1, att1, b1, h1);

    // ---- layer 2: fused GEMM pair + aggregation ----
    gemm_mma<64><<<dim3(1, mrows), 256>>>(h1, bt2h, bt2l, xl2, xr2, NODES);
    k_agg2<<<(NODES + 7) / 8, 256>>>(rowptr, csrc, xl2, xr2, att2, b2, h2);

    // ---- classifier head ----
    k_final<<<(NODES * NC + 255) / 256, 256>>>(h2, Wlin, blin, out);
}

// round 5
// speedup vs baseline: 6.4155x; 1.0314x over previous
#include <cuda_runtime.h>
#include <cuda_bf16.h>
#include <math.h>
#include <stdint.h>

// ---------------- problem constants ----------------
constexpr int NODES = 50000;
constexpr int EDGES = 800000;
constexpr int E2    = EDGES + NODES;   // 850000
constexpr int INCH  = 256;
constexpr int OUTC  = 64;
constexpr int HC    = 256;             // 4 heads * 64
constexpr int NC    = 10;
constexpr float NEG = 0.2f;
constexpr int NB_SCAN = (NODES + 1023) / 1024;  // 49

// ---------------- scratch ----------------
__device__ float g_xl1[(size_t)NODES * HC];
__device__ float g_xr1[(size_t)NODES * HC];
__device__ float g_h1 [(size_t)NODES * HC];
__device__ float g_xl2[(size_t)NODES * OUTC];
__device__ float g_xr2[(size_t)NODES * OUTC];
__device__ float g_h2 [(size_t)NODES * OUTC];
__device__ int   g_deg[NODES];
__device__ int   g_scan[NODES];
__device__ int   g_rowptr[NODES + 1];
__device__ int   g_cursor[NODES];
__device__ int   g_csrc[E2];
__device__ int   g_bsum[64];
__device__ int   g_boff[64];
// transposed + bf16 hi/lo split weights: layer1 [512][256], layer2 [128][256]
__device__ __nv_bfloat16 g_bt1_hi[512 * 256];
__device__ __nv_bfloat16 g_bt1_lo[512 * 256];
__device__ __nv_bfloat16 g_bt2_hi[128 * 256];
__device__ __nv_bfloat16 g_bt2_lo[128 * 256];

__device__ __forceinline__ float lrelu(float v) { return v > 0.f ? v : NEG * v; }

__device__ __forceinline__ uint32_t smem_u32(const void* p) {
    uint32_t a;
    asm("{ .reg .u64 t; cvta.to.shared.u64 t, %1; cvt.u32.u64 %0, t; }" : "=r"(a) : "l"(p));
    return a;
}

__device__ __forceinline__ void ldsm_x4(uint32_t* r, uint32_t addr) {
    asm volatile("ldmatrix.sync.aligned.m8n8.x4.shared.b16 {%0,%1,%2,%3}, [%4];"
                 : "=r"(r[0]), "=r"(r[1]), "=r"(r[2]), "=r"(r[3]) : "r"(addr));
}
__device__ __forceinline__ void ldsm_x2(uint32_t* r, uint32_t addr) {
    asm volatile("ldmatrix.sync.aligned.m8n8.x2.shared.b16 {%0,%1}, [%2];"
                 : "=r"(r[0]), "=r"(r[1]) : "r"(addr));
}
__device__ __forceinline__ void mma_bf16(float* c, const uint32_t* a, const uint32_t* b) {
    asm volatile("mma.sync.aligned.m16n8k16.row.col.f32.bf16.bf16.f32 "
                 "{%0,%1,%2,%3}, {%4,%5,%6,%7}, {%8,%9}, {%0,%1,%2,%3};"
                 : "+f"(c[0]), "+f"(c[1]), "+f"(c[2]), "+f"(c[3])
                 : "r"(a[0]), "r"(a[1]), "r"(a[2]), "r"(a[3]), "r"(b[0]), "r"(b[1]));
}

// ---------------- weight prep: transpose + bf16 hi/lo split ----------------
__global__ void k_prep_B(const float* __restrict__ W0, const float* __restrict__ W1,
                         __nv_bfloat16* __restrict__ bt_hi, __nv_bfloat16* __restrict__ bt_lo,
                         int N, int K) {
    int t = blockIdx.x * blockDim.x + threadIdx.x;
    int total = 2 * N * K;
    if (t >= total) return;
    int mat = t / (N * K);
    int r = t - mat * (N * K);
    int n = r / K, k = r - n * K;
    const float* W = mat ? W1 : W0;
    float w = W[k * N + n];
    __nv_bfloat16 hi = __float2bfloat16_rn(w);
    bt_hi[t] = hi;
    bt_lo[t] = __float2bfloat16_rn(w - __bfloat162float(hi));
}

// ---------------- bf16x3 tensor-core GEMM (mma.sync) ----------------
template <int NBM>
__global__ void __launch_bounds__(256, 1) gemm_mma(const float* __restrict__ A,
                                                   const __nv_bfloat16* __restrict__ Bh,
                                                   const __nv_bfloat16* __restrict__ Bl,
                                                   float* __restrict__ C0,
                                                   float* __restrict__ C1,
                                                   int M) {
    constexpr int K = 256;
    constexpr int LDS = 40;
    __shared__ __nv_bfloat16 sAh[128 * LDS];
    __shared__ __nv_bfloat16 sAl[128 * LDS];
    __shared__ __nv_bfloat16 sBh[128 * LDS];
    __shared__ __nv_bfloat16 sBl[128 * LDS];

    int tid = threadIdx.x;
    int lane = tid & 31;
    int wid = tid >> 5;
    int warpM = wid >> 2;
    int warpN = wid & 3;
    int m0 = blockIdx.y * 128;
    int n0 = blockIdx.x * 128;

    uint32_t bAh = smem_u32(sAh), bAl = smem_u32(sAl);
    uint32_t bBh = smem_u32(sBh), bBl = smem_u32(sBl);

    float4 apf[4];
    int4 bhpf[2], blpf[2];

    auto gload = [&](int kb) {
#pragma unroll
        for (int i = 0; i < 4; i++) {
            int u = tid + 256 * i;
            int row = u >> 3, c4 = u & 7;
            apf[i] = make_float4(0.f, 0.f, 0.f, 0.f);
            if (m0 + row < M)
                apf[i] = *(const float4*)(A + (size_t)(m0 + row) * K + kb * 32 + c4 * 4);
        }
#pragma unroll
        for (int i = 0; i < 2; i++) {
            int u = tid + 256 * i;
            int row = u >> 2, c = u & 3;
            size_t g = (size_t)(n0 + row) * K + kb * 32 + c * 8;
            bhpf[i] = *(const int4*)(Bh + g);
            blpf[i] = *(const int4*)(Bl + g);
        }
    };

    auto sstore = [&]() {
#pragma unroll
        for (int i = 0; i < 4; i++) {
            int u = tid + 256 * i;
            int row = u >> 3, c4 = u & 7;
            float4 v = apf[i];
            __nv_bfloat162 h0, h1, l0, l1;
            h0.x = __float2bfloat16_rn(v.x);
            h0.y = __float2bfloat16_rn(v.y);
            h1.x = __float2bfloat16_rn(v.z);
            h1.y = __float2bfloat16_rn(v.w);
            l0.x = __float2bfloat16_rn(v.x - __bfloat162float(h0.x));
            l0.y = __float2bfloat16_rn(v.y - __bfloat162float(h0.y));
            l1.x = __float2bfloat16_rn(v.z - __bfloat162float(h1.x));
            l1.y = __float2bfloat16_rn(v.w - __bfloat162float(h1.y));
            int e = row * LDS + c4 * 4;
            *(__nv_bfloat162*)(sAh + e)     = h0;
            *(__nv_bfloat162*)(sAh + e + 2) = h1;
            *(__nv_bfloat162*)(sAl + e)     = l0;
            *(__nv_bfloat162*)(sAl + e + 2) = l1;
        }
#pragma unroll
        for (int i = 0; i < 2; i++) {
            int u = tid + 256 * i;
            int row = u >> 2, c = u & 3;
            int e = row * LDS + c * 8;
            *(int4*)(sBh + e) = bhpf[i];
            *(int4*)(sBl + e) = blpf[i];
        }
    };

    float acc[4][4][4];
#pragma unroll
    for (int f = 0; f < 4; f++)
#pragma unroll
        for (int g = 0; g < 4; g++)
#pragma unroll
            for (int q = 0; q < 4; q++) acc[f][g][q] = 0.f;

    int arow = warpM * 64 + (lane & 15);
    int akc  = (lane >> 4) << 3;
    int brow = warpN * 32 + (lane & 7);
    int bkc  = ((lane >> 3) & 1) << 3;

    gload(0);
    for (int kb = 0; kb < 8; kb++) {
        sstore();
        __syncthreads();
        if (kb < 7) gload(kb + 1);

#pragma unroll
        for (int kk = 0; kk < 2; kk++) {
            uint32_t aoff = (uint32_t)((arow * LDS + kk * 16 + akc) * 2);
            uint32_t boff = (uint32_t)((brow * LDS + kk * 16 + bkc) * 2);

            uint32_t ah[4][4], bh[4][2];
#pragma unroll
            for (int f = 0; f < 4; f++)
                ldsm_x4(ah[f], bAh + aoff + (uint32_t)(f * 16 * LDS * 2));
#pragma unroll
            for (int g = 0; g < 4; g++)
                ldsm_x2(bh[g], bBh + boff + (uint32_t)(g * 8 * LDS * 2));
#pragma unroll
            for (int f = 0; f < 4; f++)
#pragma unroll
                for (int g = 0; g < 4; g++)
                    mma_bf16(acc[f][g], ah[f], bh[g]);

            uint32_t bl[4][2];
#pragma unroll
            for (int g = 0; g < 4; g++)
                ldsm_x2(bl[g], bBl + boff + (uint32_t)(g * 8 * LDS * 2));
#pragma unroll
            for (int f = 0; f < 4; f++)
#pragma unroll
                for (int g = 0; g < 4; g++)
                    mma_bf16(acc[f][g], ah[f], bl[g]);

            uint32_t al[4][4];
#pragma unroll
            for (int f = 0; f < 4; f++)
                ldsm_x4(al[f], bAl + aoff + (uint32_t)(f * 16 * LDS * 2));
#pragma unroll
            for (int f = 0; f < 4; f++)
#pragma unroll
                for (int g = 0; g < 4; g++)
                    mma_bf16(acc[f][g], al[f], bh[g]);
        }
        __syncthreads();
    }

#pragma unroll
    for (int f = 0; f < 4; f++) {
#pragma unroll
        for (int g = 0; g < 4; g++) {
            int row = m0 + warpM * 64 + f * 16 + (lane >> 2);
            int col = n0 + warpN * 32 + g * 8 + (lane & 3) * 2;
            int mat = col / NBM;
            int cc = col - mat * NBM;
            float* Cp = mat ? C1 : C0;
            if (row < M) {
                float2 v = make_float2(acc[f][g][0], acc[f][g][1]);
                *(float2*)(Cp + (size_t)row * NBM + cc) = v;
            }
            if (row + 8 < M) {
                float2 v = make_float2(acc[f][g][2], acc[f][g][3]);
                *(float2*)(Cp + (size_t)(row + 8) * NBM + cc) = v;
            }
        }
    }
}

// ---------------- CSR build ----------------
__global__ void k_zero_deg() {
    int i = blockIdx.x * blockDim.x + threadIdx.x;
    if (i < NODES) g_deg[i] = 0;
}

__global__ void k_hist(const int* __restrict__ ei) {
    int e = blockIdx.x * blockDim.x + threadIdx.x;
    if (e >= E2) return;
    int dst = (e < EDGES) ? ei[EDGES + e] : (e - EDGES);
    atomicAdd(&g_deg[dst], 1);
}

__global__ void __launch_bounds__(1024) k_scan1() {
    __shared__ int sm[1024];
    int t = threadIdx.x;
    int i = blockIdx.x * 1024 + t;
    int v = (i < NODES) ? g_deg[i] : 0;
    sm[t] = v;
    __syncthreads();
#pragma unroll
    for (int d = 1; d < 1024; d <<= 1) {
        int x = (t >= d) ? sm[t - d] : 0;
        __syncthreads();
        sm[t] += x;
        __syncthreads();
    }
    if (i < NODES) g_scan[i] = sm[t];
    if (t == 1023) g_bsum[blockIdx.x] = sm[1023];
}

__global__ void k_scan2() {
    __shared__ int sm[64];
    int t = threadIdx.x;
    int v = (t < NB_SCAN) ? g_bsum[t] : 0;
    sm[t] = v;
    __syncthreads();
#pragma unroll
    for (int d = 1; d < 64; d <<= 1) {
        int x = (t >= d) ? sm[t - d] : 0;
        __syncthreads();
        sm[t] += x;
        __syncthreads();
    }
    g_boff[t] = sm[t] - v;
}

__global__ void __launch_bounds__(1024) k_scan3() {
    int t = threadIdx.x;
    int i = blockIdx.x * 1024 + t;
    if (i >= NODES) return;
    int incl = g_scan[i] + g_boff[blockIdx.x];
    int excl = incl - g_deg[i];
    g_rowptr[i] = excl;
    g_cursor[i] = excl;
    if (i == NODES - 1) g_rowptr[NODES] = incl;
}

__global__ void k_fill(const int* __restrict__ ei) {
    int e = blockIdx.x * blockDim.x + threadIdx.x;
    if (e >= E2) return;
    int src, dst;
    if (e < EDGES) { src = ei[e]; dst = ei[EDGES + e]; }
    else           { src = e - EDGES; dst = src; }
    int pos = atomicAdd(&g_cursor[dst], 1);
    g_csrc[pos] = src;
}

// ---------------- fused GATv2 aggregation, layer 1 (H=4, C=64) ----------------
__global__ void __launch_bounds__(256) k_agg1(const int* __restrict__ rowptr,
                                              const int* __restrict__ csrc,
                                              const float* __restrict__ xl,
                                              const float* __restrict__ xr,
                                              const float* __restrict__ att,
                                              const float* __restrict__ bias,
                                              float* __restrict__ out) {
    int warp = (blockIdx.x * blockDim.x + threadIdx.x) >> 5;
    int lane = threadIdx.x & 31;
    if (warp >= NODES) return;
    int n = warp;
    int off = lane * 8;

    const float4* pr = (const float4*)(xr + (size_t)n * HC + off);
    float4 r0 = pr[0], r1 = pr[1];
    const float4* pa = (const float4*)(att + off);
    float4 a0 = pa[0], a1 = pa[1];

    float m = -INFINITY, s = 0.f;
    float acc[8] = {0.f, 0.f, 0.f, 0.f, 0.f, 0.f, 0.f, 0.f};

    int b = rowptr[n], e = rowptr[n + 1];
    for (int kb = b; kb < e; kb += 32) {
        int idx = kb + lane;
        int mysrc = (idx < e) ? csrc[idx] : 0;
        int cnt = min(32, e - kb);
        for (int j = 0; j < cnt; j++) {
            int src = __shfl_sync(0xffffffffu, mysrc, j);
            const float4* pl = (const float4*)(xl + (size_t)src * HC + off);
            float4 v0 = pl[0], v1 = pl[1];
            float p = lrelu(v0.x + r0.x) * a0.x + lrelu(v0.y + r0.y) * a0.y
                    + lrelu(v0.z + r0.z) * a0.z + lrelu(v0.w + r0.w) * a0.w
                    + lrelu(v1.x + r1.x) * a1.x + lrelu(v1.y + r1.y) * a1.y
                    + lrelu(v1.z + r1.z) * a1.z + lrelu(v1.w + r1.w) * a1.w;
            p += __shfl_xor_sync(0xffffffffu, p, 1);
            p += __shfl_xor_sync(0xffffffffu, p, 2);
            p += __shfl_xor_sync(0xffffffffu, p, 4);
            float w;
            if (p > m) {
                float f = __expf(m - p);
                s *= f;
#pragma unroll
                for (int q = 0; q < 8; q++) acc[q] *= f;
                m = p;
                w = 1.0f;
            } else {
                w = __expf(p - m);
            }
            s += w;
            acc[0] += w * v0.x; acc[1] += w * v0.y; acc[2] += w * v0.z; acc[3] += w * v0.w;
            acc[4] += w * v1.x; acc[5] += w * v1.y; acc[6] += w * v1.z; acc[7] += w * v1.w;
        }
    }
    float inv = 1.0f / s;
    const float4* pb = (const float4*)(bias + off);
    float4 b0 = pb[0], b1 = pb[1];
    float4 o0, o1;
    o0.x = fmaxf(acc[0] * inv + b0.x, 0.f);
    o0.y = fmaxf(acc[1] * inv + b0.y, 0.f);
    o0.z = fmaxf(acc[2] * inv + b0.z, 0.f);
    o0.w = fmaxf(acc[3] * inv + b0.w, 0.f);
    o1.x = fmaxf(acc[4] * inv + b1.x, 0.f);
    o1.y = fmaxf(acc[5] * inv + b1.y, 0.f);
    o1.z = fmaxf(acc[6] * inv + b1.z, 0.f);
    o1.w = fmaxf(acc[7] * inv + b1.w, 0.f);
    float4* po = (float4*)(out + (size_t)n * HC + off);
    po[0] = o0; po[1] = o1;
}

// ---------------- fused GATv2 aggregation, layer 2 (H=1, C=64) ----------------
__global__ void __launch_bounds__(256) k_agg2(const int* __restrict__ rowptr,
                                              const int* __restrict__ csrc,
                                              const float* __restrict__ xl,
                                              const float* __restrict__ xr,
                                              const float* __restrict__ att,
                                              const float* __restrict__ bias,
                                              float* __restrict__ out) {
    int warp = (blockIdx.x * blockDim.x + threadIdx.x) >> 5;
    int lane = threadIdx.x & 31;
    if (warp >= NODES) return;
    int n = warp;
    int off = lane * 2;

    float2 r = *(const float2*)(xr + (size_t)n * OUTC + off);
    float2 a = *(const float2*)(att + off);

    float m = -INFINITY, s = 0.f;
    float acc0 = 0.f, acc1 = 0.f;

    int b = rowptr[n], e = rowptr[n + 1];
    for (int kb = b; kb < e; kb += 32) {
        int idx = kb + lane;
        int mysrc = (idx < e) ? csrc[idx] : 0;
        int cnt = min(32, e - kb);
        for (int j = 0; j < cnt; j++) {
            int src = __shfl_sync(0xffffffffu, mysrc, j);
            float2 v = *(const float2*)(xl + (size_t)src * OUTC + off);
            float p = lrelu(v.x + r.x) * a.x + lrelu(v.y + r.y) * a.y;
            p += __shfl_xor_sync(0xffffffffu, p, 1);
            p += __shfl_xor_sync(0xffffffffu, p, 2);
            p += __shfl_xor_sync(0xffffffffu, p, 4);
            p += __shfl_xor_sync(0xffffffffu, p, 8);
            p += __shfl_xor_sync(0xffffffffu, p, 16);
            float w;
            if (p > m) {
                float f = __expf(m - p);
                s *= f; acc0 *= f; acc1 *= f;
                m = p; w = 1.0f;
            } else {
                w = __expf(p - m);
            }
            s += w;
            acc0 += w * v.x;
            acc1 += w * v.y;
        }
    }
    float inv = 1.0f / s;
    float2 bb = *(const float2*)(bias + off);
    float2 o;
    o.x = fmaxf(acc0 * inv + bb.x, 0.f);
    o.y = fmaxf(acc1 * inv + bb.y, 0.f);
    *(float2*)(out + (size_t)n * OUTC + off) = o;
}

// ---------------- final linear ----------------
__global__ void __launch_bounds__(256) k_final(const float* __restrict__ h2,
                                               const float* __restrict__ Wlin,
                                               const float* __restrict__ blin,
                                               float* __restrict__ out) {
    __shared__ float sW[OUTC * NC];
    __shared__ float sb[NC];
    for (int i = threadIdx.x; i < OUTC * NC; i += blockDim.x) sW[i] = Wlin[i];
    if (threadIdx.x < NC) sb[threadIdx.x] = blin[threadIdx.x];
    __syncthreads();
    int t = blockIdx.x * blockDim.x + threadIdx.x;
    if (t >= NODES * NC) return;
    int n = t / NC, c = t - n * NC;
    float sacc = sb[c];
    const float* hr = h2 + (size_t)n * OUTC;
#pragma unroll
    for (int k = 0; k < OUTC; k++)
        sacc += hr[k] * sW[k * NC + c];
    out[t] = sacc;
}

// ---------------- launch ----------------
extern "C" void kernel_launch(void* const* d_in, const int* in_sizes, int n_in,
                              void* d_out, int out_size) {
    const float* x    = (const float*)d_in[0];
    const int*   ei   = (const int*)d_in[1];
    const float* Wl1  = (const float*)d_in[2];
    const float* Wr1  = (const float*)d_in[3];
    const float* att1 = (const float*)d_in[4];
    const float* b1   = (const float*)d_in[5];
    const float* Wl2  = (const float*)d_in[6];
    const float* Wr2  = (const float*)d_in[7];
    const float* att2 = (const float*)d_in[8];
    const float* b2   = (const float*)d_in[9];
    const float* Wlin = (const float*)d_in[10];
    const float* blin = (const float*)d_in[11];
    float* out = (float*)d_out;

    float *xl1, *xr1, *h1, *xl2, *xr2, *h2;
    __nv_bfloat16 *bt1h, *bt1l, *bt2h, *bt2l;
    int *rowptr, *csrc;
    cudaGetSymbolAddress((void**)&xl1, g_xl1);
    cudaGetSymbolAddress((void**)&xr1, g_xr1);
    cudaGetSymbolAddress((void**)&h1,  g_h1);
    cudaGetSymbolAddress((void**)&xl2, g_xl2);
    cudaGetSymbolAddress((void**)&xr2, g_xr2);
    cudaGetSymbolAddress((void**)&h2,  g_h2);
    cudaGetSymbolAddress((void**)&rowptr, g_rowptr);
    cudaGetSymbolAddress((void**)&csrc,   g_csrc);
    cudaGetSymbolAddress((void**)&bt1h, g_bt1_hi);
    cudaGetSymbolAddress((void**)&bt1l, g_bt1_lo);
    cudaGetSymbolAddress((void**)&bt2h, g_bt2_hi);
    cudaGetSymbolAddress((void**)&bt2l, g_bt2_lo);

    // host-side resources, created once (device work is identical on every call)
    static cudaStream_t s2 = nullptr;
    static cudaEvent_t ev_fork = nullptr, ev_join = nullptr;
    if (!s2) {
        cudaStreamCreateWithFlags(&s2, cudaStreamNonBlocking);
        cudaEventCreateWithFlags(&ev_fork, cudaEventDisableTiming);
        cudaEventCreateWithFlags(&ev_join, cudaEventDisableTiming);
    }

    int ethreads = (E2 + 255) / 256;
    int mrows = (NODES + 127) / 128;   // 391

    // ---- fork: CSR build + layer-2 weight prep run concurrently with prep1+gemm1 ----
    cudaEventRecord(ev_fork, 0);
    cudaStreamWaitEvent(s2, ev_fork, 0);

    // branch B (stream s2): CSR chain + prep2
    k_zero_deg<<<(NODES + 255) / 256, 256, 0, s2>>>();
    k_hist<<<ethreads, 256, 0, s2>>>(ei);
    k_scan1<<<NB_SCAN, 1024, 0, s2>>>();
    k_scan2<<<1, 64, 0, s2>>>();
    k_scan3<<<NB_SCAN, 1024, 0, s2>>>();
    k_fill<<<ethreads, 256, 0, s2>>>(ei);
    k_prep_B<<<(2 * 64 * 256 + 255) / 256, 256, 0, s2>>>(Wl2, Wr2, bt2h, bt2l, 64, 256);
    cudaEventRecord(ev_join, s2);

    // branch A (capture stream): prep1 + gemm1
    k_prep_B<<<(2 * 256 * 256 + 255) / 256, 256>>>(Wl1, Wr1, bt1h, bt1l, 256, 256);
    gemm_mma<256><<<dim3(4, mrows), 256>>>(x, bt1h, bt1l, xl1, xr1, NODES);

    // ---- join: aggregation needs both CSR and gemm1 ----
    cudaStreamWaitEvent(0, ev_join, 0);

    k_agg1<<<(NODES + 7) / 8, 256>>>(rowptr, csrc, xl1, xr1, att1, b1, h1);

    // ---- layer 2 ----
    gemm_mma<64><<<dim3(1, mrows), 256>>>(h1, bt2h, bt2l, xl2, xr2, NODES);
    k_agg2<<<(NODES + 7) / 8, 256>>>(rowptr, csrc, xl2, xr2, att2, b2, h2);

    // ---- classifier head ----
    k_final<<<(NODES * NC + 255) / 256, 256>>>(h2, Wlin, blin, out);
}

// round 6
// speedup vs baseline: 6.8157x; 1.0624x over previous
#include <cuda_runtime.h>
#include <cuda_bf16.h>
#include <math.h>
#include <stdint.h>

// ---------------- problem constants ----------------
constexpr int NODES = 50000;
constexpr int EDGES = 800000;
constexpr int E2    = EDGES + NODES;   // 850000
constexpr int INCH  = 256;
constexpr int OUTC  = 64;
constexpr int HC    = 256;             // 4 heads * 64
constexpr int NC    = 10;
constexpr float NEG = 0.2f;
constexpr int NB_SCAN = (NODES + 1023) / 1024;  // 49

// ---------------- scratch ----------------
__device__ float g_xl1[(size_t)NODES * HC];
__device__ float g_xr1[(size_t)NODES * HC];
__device__ float g_h1 [(size_t)NODES * HC];
__device__ float g_xl2[(size_t)NODES * OUTC];
__device__ float g_xr2[(size_t)NODES * OUTC];
__device__ int   g_deg[NODES];
__device__ int   g_rowptr[NODES + 1];
__device__ int   g_cursor[NODES];
__device__ int   g_csrc[E2];
// transposed + bf16 hi/lo split weights
__device__ __nv_bfloat16 g_bt1_hi[512 * 256];
__device__ __nv_bfloat16 g_bt1_lo[512 * 256];
__device__ __nv_bfloat16 g_bt2_hi[128 * 256];
__device__ __nv_bfloat16 g_bt2_lo[128 * 256];

__device__ __forceinline__ float lrelu(float v) { return v > 0.f ? v : NEG * v; }

__device__ __forceinline__ uint32_t smem_u32(const void* p) {
    uint32_t a;
    asm("{ .reg .u64 t; cvta.to.shared.u64 t, %1; cvt.u32.u64 %0, t; }" : "=r"(a) : "l"(p));
    return a;
}

__device__ __forceinline__ void ldsm_x4(uint32_t* r, uint32_t addr) {
    asm volatile("ldmatrix.sync.aligned.m8n8.x4.shared.b16 {%0,%1,%2,%3}, [%4];"
                 : "=r"(r[0]), "=r"(r[1]), "=r"(r[2]), "=r"(r[3]) : "r"(addr));
}
__device__ __forceinline__ void ldsm_x2(uint32_t* r, uint32_t addr) {
    asm volatile("ldmatrix.sync.aligned.m8n8.x2.shared.b16 {%0,%1}, [%2];"
                 : "=r"(r[0]), "=r"(r[1]) : "r"(addr));
}
__device__ __forceinline__ void mma_bf16(float* c, const uint32_t* a, const uint32_t* b) {
    asm volatile("mma.sync.aligned.m16n8k16.row.col.f32.bf16.bf16.f32 "
                 "{%0,%1,%2,%3}, {%4,%5,%6,%7}, {%8,%9}, {%0,%1,%2,%3};"
                 : "+f"(c[0]), "+f"(c[1]), "+f"(c[2]), "+f"(c[3])
                 : "r"(a[0]), "r"(a[1]), "r"(a[2]), "r"(a[3]), "r"(b[0]), "r"(b[1]));
}

// ---------------- weight prep: transpose + bf16 hi/lo split ----------------
__global__ void k_prep_B(const float* __restrict__ W0, const float* __restrict__ W1,
                         __nv_bfloat16* __restrict__ bt_hi, __nv_bfloat16* __restrict__ bt_lo,
                         int N, int K) {
    int t = blockIdx.x * blockDim.x + threadIdx.x;
    int total = 2 * N * K;
    if (t >= total) return;
    int mat = t / (N * K);
    int r = t - mat * (N * K);
    int n = r / K, k = r - n * K;
    const float* W = mat ? W1 : W0;
    float w = W[k * N + n];
    __nv_bfloat16 hi = __float2bfloat16_rn(w);
    bt_hi[t] = hi;
    bt_lo[t] = __float2bfloat16_rn(w - __bfloat162float(hi));
}

// ---------------- bf16x3 tensor-core GEMM (mma.sync) ----------------
template <int NBM>
__global__ void __launch_bounds__(256, 1) gemm_mma(const float* __restrict__ A,
                                                   const __nv_bfloat16* __restrict__ Bh,
                                                   const __nv_bfloat16* __restrict__ Bl,
                                                   float* __restrict__ C0,
                                                   float* __restrict__ C1,
                                                   int M) {
    constexpr int K = 256;
    constexpr int LDS = 40;
    __shared__ __nv_bfloat16 sAh[128 * LDS];
    __shared__ __nv_bfloat16 sAl[128 * LDS];
    __shared__ __nv_bfloat16 sBh[128 * LDS];
    __shared__ __nv_bfloat16 sBl[128 * LDS];

    int tid = threadIdx.x;
    int lane = tid & 31;
    int wid = tid >> 5;
    int warpM = wid >> 2;
    int warpN = wid & 3;
    int m0 = blockIdx.y * 128;
    int n0 = blockIdx.x * 128;

    uint32_t bAh = smem_u32(sAh), bAl = smem_u32(sAl);
    uint32_t bBh = smem_u32(sBh), bBl = smem_u32(sBl);

    float4 apf[4];
    int4 bhpf[2], blpf[2];

    auto gload = [&](int kb) {
#pragma unroll
        for (int i = 0; i < 4; i++) {
            int u = tid + 256 * i;
            int row = u >> 3, c4 = u & 7;
            apf[i] = make_float4(0.f, 0.f, 0.f, 0.f);
            if (m0 + row < M)
                apf[i] = *(const float4*)(A + (size_t)(m0 + row) * K + kb * 32 + c4 * 4);
        }
#pragma unroll
        for (int i = 0; i < 2; i++) {
            int u = tid + 256 * i;
            int row = u >> 2, c = u & 3;
            size_t g = (size_t)(n0 + row) * K + kb * 32 + c * 8;
            bhpf[i] = *(const int4*)(Bh + g);
            blpf[i] = *(const int4*)(Bl + g);
        }
    };

    auto sstore = [&]() {
#pragma unroll
        for (int i = 0; i < 4; i++) {
            int u = tid + 256 * i;
            int row = u >> 3, c4 = u & 7;
            float4 v = apf[i];
            __nv_bfloat162 h0, h1, l0, l1;
            h0.x = __float2bfloat16_rn(v.x);
            h0.y = __float2bfloat16_rn(v.y);
            h1.x = __float2bfloat16_rn(v.z);
            h1.y = __float2bfloat16_rn(v.w);
            l0.x = __float2bfloat16_rn(v.x - __bfloat162float(h0.x));
            l0.y = __float2bfloat16_rn(v.y - __bfloat162float(h0.y));
            l1.x = __float2bfloat16_rn(v.z - __bfloat162float(h1.x));
            l1.y = __float2bfloat16_rn(v.w - __bfloat162float(h1.y));
            int e = row * LDS + c4 * 4;
            *(__nv_bfloat162*)(sAh + e)     = h0;
            *(__nv_bfloat162*)(sAh + e + 2) = h1;
            *(__nv_bfloat162*)(sAl + e)     = l0;
            *(__nv_bfloat162*)(sAl + e + 2) = l1;
        }
#pragma unroll
        for (int i = 0; i < 2; i++) {
            int u = tid + 256 * i;
            int row = u >> 2, c = u & 3;
            int e = row * LDS + c * 8;
            *(int4*)(sBh + e) = bhpf[i];
            *(int4*)(sBl + e) = blpf[i];
        }
    };

    float acc[4][4][4];
#pragma unroll
    for (int f = 0; f < 4; f++)
#pragma unroll
        for (int g = 0; g < 4; g++)
#pragma unroll
            for (int q = 0; q < 4; q++) acc[f][g][q] = 0.f;

    int arow = warpM * 64 + (lane & 15);
    int akc  = (lane >> 4) << 3;
    int brow = warpN * 32 + (lane & 7);
    int bkc  = ((lane >> 3) & 1) << 3;

    gload(0);
    for (int kb = 0; kb < 8; kb++) {
        sstore();
        __syncthreads();
        if (kb < 7) gload(kb + 1);

#pragma unroll
        for (int kk = 0; kk < 2; kk++) {
            uint32_t aoff = (uint32_t)((arow * LDS + kk * 16 + akc) * 2);
            uint32_t boff = (uint32_t)((brow * LDS + kk * 16 + bkc) * 2);

            uint32_t ah[4][4], bh[4][2];
#pragma unroll
            for (int f = 0; f < 4; f++)
                ldsm_x4(ah[f], bAh + aoff + (uint32_t)(f * 16 * LDS * 2));
#pragma unroll
            for (int g = 0; g < 4; g++)
                ldsm_x2(bh[g], bBh + boff + (uint32_t)(g * 8 * LDS * 2));
#pragma unroll
            for (int f = 0; f < 4; f++)
#pragma unroll
                for (int g = 0; g < 4; g++)
                    mma_bf16(acc[f][g], ah[f], bh[g]);

            uint32_t bl[4][2];
#pragma unroll
            for (int g = 0; g < 4; g++)
                ldsm_x2(bl[g], bBl + boff + (uint32_t)(g * 8 * LDS * 2));
#pragma unroll
            for (int f = 0; f < 4; f++)
#pragma unroll
                for (int g = 0; g < 4; g++)
                    mma_bf16(acc[f][g], ah[f], bl[g]);

            uint32_t al[4][4];
#pragma unroll
            for (int f = 0; f < 4; f++)
                ldsm_x4(al[f], bAl + aoff + (uint32_t)(f * 16 * LDS * 2));
#pragma unroll
            for (int f = 0; f < 4; f++)
#pragma unroll
                for (int g = 0; g < 4; g++)
                    mma_bf16(acc[f][g], al[f], bh[g]);
        }
        __syncthreads();
    }

#pragma unroll
    for (int f = 0; f < 4; f++) {
#pragma unroll
        for (int g = 0; g < 4; g++) {
            int row = m0 + warpM * 64 + f * 16 + (lane >> 2);
            int col = n0 + warpN * 32 + g * 8 + (lane & 3) * 2;
            int mat = col / NBM;
            int cc = col - mat * NBM;
            float* Cp = mat ? C1 : C0;
            if (row < M) {
                float2 v = make_float2(acc[f][g][0], acc[f][g][1]);
                *(float2*)(Cp + (size_t)row * NBM + cc) = v;
            }
            if (row + 8 < M) {
                float2 v = make_float2(acc[f][g][2], acc[f][g][3]);
                *(float2*)(Cp + (size_t)(row + 8) * NBM + cc) = v;
            }
        }
    }
}

// ---------------- CSR build (vectorized hist / fused scan / vectorized fill) ----------------
// self-loops are NOT counted in hist; the scan adds +1 per node.
__global__ void k_hist(const int* __restrict__ ei) {
    int t = blockIdx.x * blockDim.x + threadIdx.x;
    int e4 = t * 4;
    if (e4 + 3 < EDGES) {
        int4 d = *(const int4*)(ei + EDGES + e4);
        atomicAdd(&g_deg[d.x], 1);
        atomicAdd(&g_deg[d.y], 1);
        atomicAdd(&g_deg[d.z], 1);
        atomicAdd(&g_deg[d.w], 1);
    } else if (e4 < EDGES) {
        for (int e = e4; e < EDGES; e++) atomicAdd(&g_deg[ei[EDGES + e]], 1);
    }
}

// single-block fused scan: rowptr/cursor from deg(+1 self loop)
__global__ void __launch_bounds__(1024) k_scan_all() {
    __shared__ int wsum[32];
    int tid = threadIdx.x;
    int lane = tid & 31, w = tid >> 5;
    int running = 0;
    for (int chunk = 0; chunk < NB_SCAN; chunk++) {
        int i = chunk * 1024 + tid;
        int v = (i < NODES) ? (g_deg[i] + 1) : 0;   // +1 = self loop
        int x = v;
#pragma unroll
        for (int d = 1; d < 32; d <<= 1) {
            int y = __shfl_up_sync(0xffffffffu, x, d);
            if (lane >= d) x += y;
        }
        if (lane == 31) wsum[w] = x;
        __syncthreads();
        if (w == 0) {
            int tsum = wsum[lane];
#pragma unroll
            for (int d = 1; d < 32; d <<= 1) {
                int y = __shfl_up_sync(0xffffffffu, tsum, d);
                if (lane >= d) tsum += y;
            }
            wsum[lane] = tsum;
        }
        __syncthreads();
        int incl = x + (w > 0 ? wsum[w - 1] : 0) + running;
        if (i < NODES) {
            g_rowptr[i] = incl - v;
            g_cursor[i] = incl - v;
            if (i == NODES - 1) g_rowptr[NODES] = incl;
        }
        running += wsum[31];
        __syncthreads();
    }
}

__global__ void k_fill(const int* __restrict__ ei) {
    int t = blockIdx.x * blockDim.x + threadIdx.x;
    constexpr int EQ = EDGES / 4;   // 200000
    if (t < EQ) {
        int e4 = t * 4;
        int4 s = *(const int4*)(ei + e4);
        int4 d = *(const int4*)(ei + EDGES + e4);
        g_csrc[atomicAdd(&g_cursor[d.x], 1)] = s.x;
        g_csrc[atomicAdd(&g_cursor[d.y], 1)] = s.y;
        g_csrc[atomicAdd(&g_cursor[d.z], 1)] = s.z;
        g_csrc[atomicAdd(&g_cursor[d.w], 1)] = s.w;
    } else if (t < EQ + NODES) {
        int i = t - EQ;                     // self loop
        g_csrc[atomicAdd(&g_cursor[i], 1)] = i;
    }
}

// ---------------- fused GATv2 aggregation, layer 1 (H=4, C=64) ----------------
// One warp per node, unroll-by-2 online softmax.
__global__ void __launch_bounds__(256) k_agg1(const int* __restrict__ rowptr,
                                              const int* __restrict__ csrc,
                                              const float* __restrict__ xl,
                                              const float* __restrict__ xr,
                                              const float* __restrict__ att,
                                              const float* __restrict__ bias,
                                              float* __restrict__ out) {
    int warp = (blockIdx.x * blockDim.x + threadIdx.x) >> 5;
    int lane = threadIdx.x & 31;
    if (warp >= NODES) return;
    int n = warp;
    int off = lane * 8;

    const float4* pr = (const float4*)(xr + (size_t)n * HC + off);
    float4 r0 = pr[0], r1 = pr[1];
    const float4* pa = (const float4*)(att + off);
    float4 a0 = pa[0], a1 = pa[1];

    float m = -INFINITY, s = 0.f;
    float acc[8] = {0.f, 0.f, 0.f, 0.f, 0.f, 0.f, 0.f, 0.f};

    int b = rowptr[n], e = rowptr[n + 1];
    for (int kb = b; kb < e; kb += 32) {
        int idx = kb + lane;
        int mysrc = (idx < e) ? csrc[idx] : 0;
        int cnt = min(32, e - kb);
        int j = 0;
        for (; j + 1 < cnt; j += 2) {
            int s0 = __shfl_sync(0xffffffffu, mysrc, j);
            int s1 = __shfl_sync(0xffffffffu, mysrc, j + 1);
            const float4* p0 = (const float4*)(xl + (size_t)s0 * HC + off);
            const float4* p1 = (const float4*)(xl + (size_t)s1 * HC + off);
            float4 u0 = p0[0], u1 = p0[1];
            float4 t0 = p1[0], t1 = p1[1];
            float q0 = lrelu(u0.x + r0.x) * a0.x + lrelu(u0.y + r0.y) * a0.y
                     + lrelu(u0.z + r0.z) * a0.z + lrelu(u0.w + r0.w) * a0.w
                     + lrelu(u1.x + r1.x) * a1.x + lrelu(u1.y + r1.y) * a1.y
                     + lrelu(u1.z + r1.z) * a1.z + lrelu(u1.w + r1.w) * a1.w;
            float q1 = lrelu(t0.x + r0.x) * a0.x + lrelu(t0.y + r0.y) * a0.y
                     + lrelu(t0.z + r0.z) * a0.z + lrelu(t0.w + r0.w) * a0.w
                     + lrelu(t1.x + r1.x) * a1.x + lrelu(t1.y + r1.y) * a1.y
                     + lrelu(t1.z + r1.z) * a1.z + lrelu(t1.w + r1.w) * a1.w;
            q0 += __shfl_xor_sync(0xffffffffu, q0, 1);
            q1 += __shfl_xor_sync(0xffffffffu, q1, 1);
            q0 += __shfl_xor_sync(0xffffffffu, q0, 2);
            q1 += __shfl_xor_sync(0xffffffffu, q1, 2);
            q0 += __shfl_xor_sync(0xffffffffu, q0, 4);
            q1 += __shfl_xor_sync(0xffffffffu, q1, 4);
            float pmax = fmaxf(q0, q1);
            if (pmax > m) {
                float f = __expf(m - pmax);   // m=-inf -> 0
                s *= f;
#pragma unroll
                for (int q = 0; q < 8; q++) acc[q] *= f;
                m = pmax;
            }
            float w0 = __expf(q0 - m), w1 = __expf(q1 - m);
            s += w0 + w1;
            acc[0] += w0 * u0.x + w1 * t0.x;
            acc[1] += w0 * u0.y + w1 * t0.y;
            acc[2] += w0 * u0.z + w1 * t0.z;
            acc[3] += w0 * u0.w + w1 * t0.w;
            acc[4] += w0 * u1.x + w1 * t1.x;
            acc[5] += w0 * u1.y + w1 * t1.y;
            acc[6] += w0 * u1.z + w1 * t1.z;
            acc[7] += w0 * u1.w + w1 * t1.w;
        }
        if (j < cnt) {
            int s0 = __shfl_sync(0xffffffffu, mysrc, j);
            const float4* p0 = (const float4*)(xl + (size_t)s0 * HC + off);
            float4 u0 = p0[0], u1 = p0[1];
            float q0 = lrelu(u0.x + r0.x) * a0.x + lrelu(u0.y + r0.y) * a0.y
                     + lrelu(u0.z + r0.z) * a0.z + lrelu(u0.w + r0.w) * a0.w
                     + lrelu(u1.x + r1.x) * a1.x + lrelu(u1.y + r1.y) * a1.y
                     + lrelu(u1.z + r1.z) * a1.z + lrelu(u1.w + r1.w) * a1.w;
            q0 += __shfl_xor_sync(0xffffffffu, q0, 1);
            q0 += __shfl_xor_sync(0xffffffffu, q0, 2);
            q0 += __shfl_xor_sync(0xffffffffu, q0, 4);
            if (q0 > m) {
                float f = __expf(m - q0);
                s *= f;
#pragma unroll
                for (int q = 0; q < 8; q++) acc[q] *= f;
                m = q0;
            }
            float w0 = __expf(q0 - m);
            s += w0;
            acc[0] += w0 * u0.x; acc[1] += w0 * u0.y; acc[2] += w0 * u0.z; acc[3] += w0 * u0.w;
            acc[4] += w0 * u1.x; acc[5] += w0 * u1.y; acc[6] += w0 * u1.z; acc[7] += w0 * u1.w;
        }
    }
    float inv = 1.0f / s;
    const float4* pb = (const float4*)(bias + off);
    float4 b0 = pb[0], b1 = pb[1];
    float4 o0, o1;
    o0.x = fmaxf(acc[0] * inv + b0.x, 0.f);
    o0.y = fmaxf(acc[1] * inv + b0.y, 0.f);
    o0.z = fmaxf(acc[2] * inv + b0.z, 0.f);
    o0.w = fmaxf(acc[3] * inv + b0.w, 0.f);
    o1.x = fmaxf(acc[4] * inv + b1.x, 0.f);
    o1.y = fmaxf(acc[5] * inv + b1.y, 0.f);
    o1.z = fmaxf(acc[6] * inv + b1.z, 0.f);
    o1.w = fmaxf(acc[7] * inv + b1.w, 0.f);
    float4* po = (float4*)(out + (size_t)n * HC + off);
    po[0] = o0; po[1] = o1;
}

// ---------------- fused GATv2 aggregation layer 2 + final linear ----------------
// One warp per node; lane handles 2 channels. Classifier head fused in epilogue.
__global__ void __launch_bounds__(256) k_agg2(const int* __restrict__ rowptr,
                                              const int* __restrict__ csrc,
                                              const float* __restrict__ xl,
                                              const float* __restrict__ xr,
                                              const float* __restrict__ att,
                                              const float* __restrict__ bias,
                                              const float* __restrict__ Wlin,
                                              const float* __restrict__ blin,
                                              float* __restrict__ out) {
    int warp = (blockIdx.x * blockDim.x + threadIdx.x) >> 5;
    int lane = threadIdx.x & 31;
    if (warp >= NODES) return;
    int n = warp;
    int off = lane * 2;

    float2 r = *(const float2*)(xr + (size_t)n * OUTC + off);
    float2 a = *(const float2*)(att + off);

    float m = -INFINITY, s = 0.f;
    float acc0 = 0.f, acc1 = 0.f;

    int b = rowptr[n], e = rowptr[n + 1];
    for (int kb = b; kb < e; kb += 32) {
        int idx = kb + lane;
        int mysrc = (idx < e) ? csrc[idx] : 0;
        int cnt = min(32, e - kb);
        int j = 0;
        for (; j + 1 < cnt; j += 2) {
            int s0 = __shfl_sync(0xffffffffu, mysrc, j);
            int s1 = __shfl_sync(0xffffffffu, mysrc, j + 1);
            float2 v0 = *(const float2*)(xl + (size_t)s0 * OUTC + off);
            float2 v1 = *(const float2*)(xl + (size_t)s1 * OUTC + off);
            float q0 = lrelu(v0.x + r.x) * a.x + lrelu(v0.y + r.y) * a.y;
            float q1 = lrelu(v1.x + r.x) * a.x + lrelu(v1.y + r.y) * a.y;
#pragma unroll
            for (int d = 1; d < 32; d <<= 1) {
                q0 += __shfl_xor_sync(0xffffffffu, q0, d);
                q1 += __shfl_xor_sync(0xffffffffu, q1, d);
            }
            float pmax = fmaxf(q0, q1);
            if (pmax > m) {
                float f = __expf(m - pmax);
                s *= f; acc0 *= f; acc1 *= f;
                m = pmax;
            }
            float w0 = __expf(q0 - m), w1 = __expf(q1 - m);
            s += w0 + w1;
            acc0 += w0 * v0.x + w1 * v1.x;
            acc1 += w0 * v0.y + w1 * v1.y;
        }
        if (j < cnt) {
            int s0 = __shfl_sync(0xffffffffu, mysrc, j);
            float2 v0 = *(const float2*)(xl + (size_t)s0 * OUTC + off);
            float q0 = lrelu(v0.x + r.x) * a.x + lrelu(v0.y + r.y) * a.y;
#pragma unroll
            for (int d = 1; d < 32; d <<= 1)
                q0 += __shfl_xor_sync(0xffffffffu, q0, d);
            if (q0 > m) {
                float f = __expf(m - q0);
                s *= f; acc0 *= f; acc1 *= f;
                m = q0;
            }
            float w0 = __expf(q0 - m);
            s += w0;
            acc0 += w0 * v0.x;
            acc1 += w0 * v0.y;
        }
    }
    float inv = 1.0f / s;
    float2 bb = *(const float2*)(bias + off);
    float hx = fmaxf(acc0 * inv + bb.x, 0.f);
    float hy = fmaxf(acc1 * inv + bb.y, 0.f);

    // fused classifier head: out[n,c] = sum_k h2[n,k]*Wlin[k,c] + blin[c]
    float part[NC];
#pragma unroll
    for (int c = 0; c < NC; c++)
        part[c] = hx * Wlin[off * NC + c] + hy * Wlin[(off + 1) * NC + c];
#pragma unroll
    for (int d = 16; d >= 1; d >>= 1)
#pragma unroll
        for (int c = 0; c < NC; c++)
            part[c] += __shfl_xor_sync(0xffffffffu, part[c], d);
    if (lane == 0) {
#pragma unroll
        for (int c = 0; c < NC; c++)
            out[(size_t)n * NC + c] = part[c] + blin[c];
    }
}

// ---------------- launch ----------------
extern "C" void kernel_launch(void* const* d_in, const int* in_sizes, int n_in,
                              void* d_out, int out_size) {
    const float* x    = (const float*)d_in[0];
    const int*   ei   = (const int*)d_in[1];
    const float* Wl1  = (const float*)d_in[2];
    const float* Wr1  = (const float*)d_in[3];
    const float* att1 = (const float*)d_in[4];
    const float* b1   = (const float*)d_in[5];
    const float* Wl2  = (const float*)d_in[6];
    const float* Wr2  = (const float*)d_in[7];
    const float* att2 = (const float*)d_in[8];
    const float* b2   = (const float*)d_in[9];
    const float* Wlin = (const float*)d_in[10];
    const float* blin = (const float*)d_in[11];
    float* out = (float*)d_out;

    float *xl1, *xr1, *h1, *xl2, *xr2, *dgp;
    __nv_bfloat16 *bt1h, *bt1l, *bt2h, *bt2l;
    int *rowptr, *csrc, *deg;
    cudaGetSymbolAddress((void**)&xl1, g_xl1);
    cudaGetSymbolAddress((void**)&xr1, g_xr1);
    cudaGetSymbolAddress((void**)&h1,  g_h1);
    cudaGetSymbolAddress((void**)&xl2, g_xl2);
    cudaGetSymbolAddress((void**)&xr2, g_xr2);
    cudaGetSymbolAddress((void**)&rowptr, g_rowptr);
    cudaGetSymbolAddress((void**)&csrc,   g_csrc);
    cudaGetSymbolAddress((void**)&deg,    g_deg);
    cudaGetSymbolAddress((void**)&bt1h, g_bt1_hi);
    cudaGetSymbolAddress((void**)&bt1l, g_bt1_lo);
    cudaGetSymbolAddress((void**)&bt2h, g_bt2_hi);
    cudaGetSymbolAddress((void**)&bt2l, g_bt2_lo);

    static cudaStream_t s2 = nullptr;
    static cudaEvent_t ev_fork = nullptr, ev_join = nullptr;
    if (!s2) {
        cudaStreamCreateWithFlags(&s2, cudaStreamNonBlocking);
        cudaEventCreateWithFlags(&ev_fork, cudaEventDisableTiming);
        cudaEventCreateWithFlags(&ev_join, cudaEventDisableTiming);
    }

    int mrows = (NODES + 127) / 128;   // 391

    // ---- fork: CSR build + layer-2 weight prep concurrent with prep1+gemm1 ----
    cudaEventRecord(ev_fork, 0);
    cudaStreamWaitEvent(s2, ev_fork, 0);

    // branch B (stream s2): CSR chain + prep2
    cudaMemsetAsync(deg, 0, NODES * sizeof(int), s2);
    k_hist<<<(EDGES / 4 + 255) / 256, 256, 0, s2>>>(ei);
    k_scan_all<<<1, 1024, 0, s2>>>();
    k_fill<<<(EDGES / 4 + NODES + 255) / 256, 256, 0, s2>>>(ei);
    k_prep_B<<<(2 * 64 * 256 + 255) / 256, 256, 0, s2>>>(Wl2, Wr2, bt2h, bt2l, 64, 256);
    cudaEventRecord(ev_join, s2);

    // branch A (capture stream): prep1 + gemm1
    k_prep_B<<<(2 * 256 * 256 + 255) / 256, 256>>>(Wl1, Wr1, bt1h, bt1l, 256, 256);
    gemm_mma<256><<<dim3(4, mrows), 256>>>(x, bt1h, bt1l, xl1, xr1, NODES);

    // ---- join ----
    cudaStreamWaitEvent(0, ev_join, 0);

    k_agg1<<<(NODES + 7) / 8, 256>>>(rowptr, csrc, xl1, xr1, att1, b1, h1);
    gemm_mma<64><<<dim3(1, mrows), 256>>>(h1, bt2h, bt2l, xl2, xr2, NODES);
    k_agg2<<<(NODES + 7) / 8, 256>>>(rowptr, csrc, xl2, xr2, att2, b2, Wlin, blin, out);
}

// round 7
// speedup vs baseline: 7.6251x; 1.1187x over previous
#include <cuda_runtime.h>
#include <cuda_fp16.h>
#include <math.h>
#include <stdint.h>

// ---------------- problem constants ----------------
constexpr int NODES = 50000;
constexpr int EDGES = 800000;
constexpr int E2    = EDGES + NODES;   // 850000
constexpr int OUTC  = 64;
constexpr int HC    = 256;             // 4 heads * 64
constexpr int NC    = 10;
constexpr float NEG = 0.2f;
constexpr int NB_SCAN = (NODES + 1023) / 1024;  // 49

// ---------------- scratch ----------------
__device__ float g_xl1[(size_t)NODES * HC];
__device__ float g_xr1[(size_t)NODES * HC];
__device__ float g_h1 [(size_t)NODES * HC];
__device__ float g_xl2[(size_t)NODES * OUTC];
__device__ float g_xr2[(size_t)NODES * OUTC];
__device__ int   g_deg[NODES];
__device__ int   g_rowptr[NODES + 1];
__device__ int   g_cursor[NODES];
__device__ int   g_csrc[E2];
// transposed + fp16 hi/lo split weights
__device__ __half g_bt1_hi[512 * 256];
__device__ __half g_bt1_lo[512 * 256];
__device__ __half g_bt2_hi[128 * 256];
__device__ __half g_bt2_lo[128 * 256];

__device__ __forceinline__ float lrelu(float v) { return v > 0.f ? v : NEG * v; }

__device__ __forceinline__ uint32_t smem_u32(const void* p) {
    uint32_t a;
    asm("{ .reg .u64 t; cvta.to.shared.u64 t, %1; cvt.u32.u64 %0, t; }" : "=r"(a) : "l"(p));
    return a;
}

__device__ __forceinline__ void ldsm_x4(uint32_t* r, uint32_t addr) {
    asm volatile("ldmatrix.sync.aligned.m8n8.x4.shared.b16 {%0,%1,%2,%3}, [%4];"
                 : "=r"(r[0]), "=r"(r[1]), "=r"(r[2]), "=r"(r[3]) : "r"(addr));
}
__device__ __forceinline__ void ldsm_x2(uint32_t* r, uint32_t addr) {
    asm volatile("ldmatrix.sync.aligned.m8n8.x2.shared.b16 {%0,%1}, [%2];"
                 : "=r"(r[0]), "=r"(r[1]) : "r"(addr));
}
__device__ __forceinline__ void mma_fp16(float* c, const uint32_t* a, const uint32_t* b) {
    asm volatile("mma.sync.aligned.m16n8k16.row.col.f32.f16.f16.f32 "
                 "{%0,%1,%2,%3}, {%4,%5,%6,%7}, {%8,%9}, {%0,%1,%2,%3};"
                 : "+f"(c[0]), "+f"(c[1]), "+f"(c[2]), "+f"(c[3])
                 : "r"(a[0]), "r"(a[1]), "r"(a[2]), "r"(a[3]), "r"(b[0]), "r"(b[1]));
}

// ---------------- weight prep: transpose + fp16 hi/lo split ----------------
__global__ void k_prep_B(const float* __restrict__ W0, const float* __restrict__ W1,
                         __half* __restrict__ bt_hi, __half* __restrict__ bt_lo,
                         int N, int K) {
    int t = blockIdx.x * blockDim.x + threadIdx.x;
    int total = 2 * N * K;
    if (t >= total) return;
    int mat = t / (N * K);
    int r = t - mat * (N * K);
    int n = r / K, k = r - n * K;
    const float* W = mat ? W1 : W0;
    float w = W[k * N + n];
    __half hi = __float2half_rn(w);
    bt_hi[t] = hi;
    bt_lo[t] = __float2half_rn(w - __half2float(hi));
}

// ---------------- fp16x2 tensor-core GEMM (mma.sync) ----------------
// C_cat[M, 2*NBM] = A[M,256] @ Bt^T; Bt=[2*NBM][256] pre-split hi/lo.
// Error-compensated: ah*bh + ah*bl (A residual dropped: ~2^-12 relative).
template <int NBM>
__global__ void __launch_bounds__(256, 1) gemm_mma(const float* __restrict__ A,
                                                   const __half* __restrict__ Bh,
                                                   const __half* __restrict__ Bl,
                                                   float* __restrict__ C0,
                                                   float* __restrict__ C1,
                                                   int M) {
    constexpr int K = 256;
    constexpr int LDS = 40;
    __shared__ __half sAh[128 * LDS];
    __shared__ __half sBh[128 * LDS];
    __shared__ __half sBl[128 * LDS];

    int tid = threadIdx.x;
    int lane = tid & 31;
    int wid = tid >> 5;
    int warpM = wid >> 2;
    int warpN = wid & 3;
    int m0 = blockIdx.y * 128;
    int n0 = blockIdx.x * 128;

    uint32_t bAh = smem_u32(sAh);
    uint32_t bBh = smem_u32(sBh), bBl = smem_u32(sBl);

    float4 apf[4];
    int4 bhpf[2], blpf[2];

    auto gload = [&](int kb) {
#pragma unroll
        for (int i = 0; i < 4; i++) {
            int u = tid + 256 * i;
            int row = u >> 3, c4 = u & 7;
            apf[i] = make_float4(0.f, 0.f, 0.f, 0.f);
            if (m0 + row < M)
                apf[i] = *(const float4*)(A + (size_t)(m0 + row) * K + kb * 32 + c4 * 4);
        }
#pragma unroll
        for (int i = 0; i < 2; i++) {
            int u = tid + 256 * i;
            int row = u >> 2, c = u & 3;
            size_t g = (size_t)(n0 + row) * K + kb * 32 + c * 8;
            bhpf[i] = *(const int4*)(Bh + g);
            blpf[i] = *(const int4*)(Bl + g);
        }
    };

    auto sstore = [&]() {
#pragma unroll
        for (int i = 0; i < 4; i++) {
            int u = tid + 256 * i;
            int row = u >> 3, c4 = u & 7;
            float4 v = apf[i];
            __half2 h0, h1;
            h0.x = __float2half_rn(v.x);
            h0.y = __float2half_rn(v.y);
            h1.x = __float2half_rn(v.z);
            h1.y = __float2half_rn(v.w);
            int e = row * LDS + c4 * 4;
            *(__half2*)(sAh + e)     = h0;
            *(__half2*)(sAh + e + 2) = h1;
        }
#pragma unroll
        for (int i = 0; i < 2; i++) {
            int u = tid + 256 * i;
            int row = u >> 2, c = u & 3;
            int e = row * LDS + c * 8;
            *(int4*)(sBh + e) = bhpf[i];
            *(int4*)(sBl + e) = blpf[i];
        }
    };

    float acc[4][4][4];
#pragma unroll
    for (int f = 0; f < 4; f++)
#pragma unroll
        for (int g = 0; g < 4; g++)
#pragma unroll
            for (int q = 0; q < 4; q++) acc[f][g][q] = 0.f;

    int arow = warpM * 64 + (lane & 15);
    int akc  = (lane >> 4) << 3;
    int brow = warpN * 32 + (lane & 7);
    int bkc  = ((lane >> 3) & 1) << 3;

    gload(0);
    for (int kb = 0; kb < 8; kb++) {
        sstore();
        __syncthreads();
        if (kb < 7) gload(kb + 1);

#pragma unroll
        for (int kk = 0; kk < 2; kk++) {
            uint32_t aoff = (uint32_t)((arow * LDS + kk * 16 + akc) * 2);
            uint32_t boff = (uint32_t)((brow * LDS + kk * 16 + bkc) * 2);

            uint32_t ah[4][4], bh[4][2];
#pragma unroll
            for (int f = 0; f < 4; f++)
                ldsm_x4(ah[f], bAh + aoff + (uint32_t)(f * 16 * LDS * 2));
#pragma unroll
            for (int g = 0; g < 4; g++)
                ldsm_x2(bh[g], bBh + boff + (uint32_t)(g * 8 * LDS * 2));
#pragma unroll
            for (int f = 0; f < 4; f++)
#pragma unroll
                for (int g = 0; g < 4; g++)
                    mma_fp16(acc[f][g], ah[f], bh[g]);

            uint32_t bl[4][2];
#pragma unroll
            for (int g = 0; g < 4; g++)
                ldsm_x2(bl[g], bBl + boff + (uint32_t)(g * 8 * LDS * 2));
#pragma unroll
            for (int f = 0; f < 4; f++)
#pragma unroll
                for (int g = 0; g < 4; g++)
                    mma_fp16(acc[f][g], ah[f], bl[g]);
        }
        __syncthreads();
    }

#pragma unroll
    for (int f = 0; f < 4; f++) {
#pragma unroll
        for (int g = 0; g < 4; g++) {
            int row = m0 + warpM * 64 + f * 16 + (lane >> 2);
            int col = n0 + warpN * 32 + g * 8 + (lane & 3) * 2;
            int mat = col / NBM;
            int cc = col - mat * NBM;
            float* Cp = mat ? C1 : C0;
            if (row < M) {
                float2 v = make_float2(acc[f][g][0], acc[f][g][1]);
                *(float2*)(Cp + (size_t)row * NBM + cc) = v;
            }
            if (row + 8 < M) {
                float2 v = make_float2(acc[f][g][2], acc[f][g][3]);
                *(float2*)(Cp + (size_t)(row + 8) * NBM + cc) = v;
            }
        }
    }
}

// ---------------- CSR build ----------------
__global__ void k_hist(const int* __restrict__ ei) {
    int t = blockIdx.x * blockDim.x + threadIdx.x;
    int e4 = t * 4;
    if (e4 + 3 < EDGES) {
        int4 d = *(const int4*)(ei + EDGES + e4);
        atomicAdd(&g_deg[d.x], 1);
        atomicAdd(&g_deg[d.y], 1);
        atomicAdd(&g_deg[d.z], 1);
        atomicAdd(&g_deg[d.w], 1);
    } else if (e4 < EDGES) {
        for (int e = e4; e < EDGES; e++) atomicAdd(&g_deg[ei[EDGES + e]], 1);
    }
}

__global__ void __launch_bounds__(1024) k_scan_all() {
    __shared__ int wsum[32];
    int tid = threadIdx.x;
    int lane = tid & 31, w = tid >> 5;
    int running = 0;
    for (int chunk = 0; chunk < NB_SCAN; chunk++) {
        int i = chunk * 1024 + tid;
        int v = (i < NODES) ? (g_deg[i] + 1) : 0;   // +1 = self loop
        int x = v;
#pragma unroll
        for (int d = 1; d < 32; d <<= 1) {
            int y = __shfl_up_sync(0xffffffffu, x, d);
            if (lane >= d) x += y;
        }
        if (lane == 31) wsum[w] = x;
        __syncthreads();
        if (w == 0) {
            int tsum = wsum[lane];
#pragma unroll
            for (int d = 1; d < 32; d <<= 1) {
                int y = __shfl_up_sync(0xffffffffu, tsum, d);
                if (lane >= d) tsum += y;
            }
            wsum[lane] = tsum;
        }
        __syncthreads();
        int incl = x + (w > 0 ? wsum[w - 1] : 0) + running;
        if (i < NODES) {
            g_rowptr[i] = incl - v;
            g_cursor[i] = incl - v;
            if (i == NODES - 1) g_rowptr[NODES] = incl;
        }
        running += wsum[31];
        __syncthreads();
    }
}

__global__ void k_fill(const int* __restrict__ ei) {
    int t = blockIdx.x * blockDim.x + threadIdx.x;
    constexpr int EQ = EDGES / 4;
    if (t < EQ) {
        int e4 = t * 4;
        int4 s = *(const int4*)(ei + e4);
        int4 d = *(const int4*)(ei + EDGES + e4);
        g_csrc[atomicAdd(&g_cursor[d.x], 1)] = s.x;
        g_csrc[atomicAdd(&g_cursor[d.y], 1)] = s.y;
        g_csrc[atomicAdd(&g_cursor[d.z], 1)] = s.z;
        g_csrc[atomicAdd(&g_cursor[d.w], 1)] = s.w;
    } else if (t < EQ + NODES) {
        int i = t - EQ;
        g_csrc[atomicAdd(&g_cursor[i], 1)] = i;
    }
}

// ---------------- fused GATv2 aggregation, layer 1 (H=4, C=64) ----------------
__global__ void __launch_bounds__(256) k_agg1(const int* __restrict__ rowptr,
                                              const int* __restrict__ csrc,
                                              const float* __restrict__ xl,
                                              const float* __restrict__ xr,
                                              const float* __restrict__ att,
                                              const float* __restrict__ bias,
                                              float* __restrict__ out) {
    int warp = (blockIdx.x * blockDim.x + threadIdx.x) >> 5;
    int lane = threadIdx.x & 31;
    if (warp >= NODES) return;
    int n = warp;
    int off = lane * 8;

    const float4* pr = (const float4*)(xr + (size_t)n * HC + off);
    float4 r0 = pr[0], r1 = pr[1];
    const float4* pa = (const float4*)(att + off);
    float4 a0 = pa[0], a1 = pa[1];

    float m = -INFINITY, s = 0.f;
    float acc[8] = {0.f, 0.f, 0.f, 0.f, 0.f, 0.f, 0.f, 0.f};

    int b = rowptr[n], e = rowptr[n + 1];
    for (int kb = b; kb < e; kb += 32) {
        int idx = kb + lane;
        int mysrc = (idx < e) ? csrc[idx] : 0;
        int cnt = min(32, e - kb);
        int j = 0;
        for (; j + 1 < cnt; j += 2) {
            int s0 = __shfl_sync(0xffffffffu, mysrc, j);
            int s1 = __shfl_sync(0xffffffffu, mysrc, j + 1);
            const float4* p0 = (const float4*)(xl + (size_t)s0 * HC + off);
            const float4* p1 = (const float4*)(xl + (size_t)s1 * HC + off);
            float4 u0 = p0[0], u1 = p0[1];
            float4 t0 = p1[0], t1 = p1[1];
            float q0 = lrelu(u0.x + r0.x) * a0.x + lrelu(u0.y + r0.y) * a0.y
                     + lrelu(u0.z + r0.z) * a0.z + lrelu(u0.w + r0.w) * a0.w
                     + lrelu(u1.x + r1.x) * a1.x + lrelu(u1.y + r1.y) * a1.y
                     + lrelu(u1.z + r1.z) * a1.z + lrelu(u1.w + r1.w) * a1.w;
            float q1 = lrelu(t0.x + r0.x) * a0.x + lrelu(t0.y + r0.y) * a0.y
                     + lrelu(t0.z + r0.z) * a0.z + lrelu(t0.w + r0.w) * a0.w
                     + lrelu(t1.x + r1.x) * a1.x + lrelu(t1.y + r1.y) * a1.y
                     + lrelu(t1.z + r1.z) * a1.z + lrelu(t1.w + r1.w) * a1.w;
            q0 += __shfl_xor_sync(0xffffffffu, q0, 1);
            q1 += __shfl_xor_sync(0xffffffffu, q1, 1);
            q0 += __shfl_xor_sync(0xffffffffu, q0, 2);
            q1 += __shfl_xor_sync(0xffffffffu, q1, 2);
            q0 += __shfl_xor_sync(0xffffffffu, q0, 4);
            q1 += __shfl_xor_sync(0xffffffffu, q1, 4);
            float pmax = fmaxf(q0, q1);
            if (pmax > m) {
                float f = __expf(m - pmax);
                s *= f;
#pragma unroll
                for (int q = 0; q < 8; q++) acc[q] *= f;
                m = pmax;
            }
            float w0 = __expf(q0 - m), w1 = __expf(q1 - m);
            s += w0 + w1;
            acc[0] += w0 * u0.x + w1 * t0.x;
            acc[1] += w0 * u0.y + w1 * t0.y;
            acc[2] += w0 * u0.z + w1 * t0.z;
            acc[3] += w0 * u0.w + w1 * t0.w;
            acc[4] += w0 * u1.x + w1 * t1.x;
            acc[5] += w0 * u1.y + w1 * t1.y;
            acc[6] += w0 * u1.z + w1 * t1.z;
            acc[7] += w0 * u1.w + w1 * t1.w;
        }
        if (j < cnt) {
            int s0 = __shfl_sync(0xffffffffu, mysrc, j);
            const float4* p0 = (const float4*)(xl + (size_t)s0 * HC + off);
            float4 u0 = p0[0], u1 = p0[1];
            float q0 = lrelu(u0.x + r0.x) * a0.x + lrelu(u0.y + r0.y) * a0.y
                     + lrelu(u0.z + r0.z) * a0.z + lrelu(u0.w + r0.w) * a0.w
                     + lrelu(u1.x + r1.x) * a1.x + lrelu(u1.y + r1.y) * a1.y
                     + lrelu(u1.z + r1.z) * a1.z + lrelu(u1.w + r1.w) * a1.w;
            q0 += __shfl_xor_sync(0xffffffffu, q0, 1);
            q0 += __shfl_xor_sync(0xffffffffu, q0, 2);
            q0 += __shfl_xor_sync(0xffffffffu, q0, 4);
            if (q0 > m) {
                float f = __expf(m - q0);
                s *= f;
#pragma unroll
                for (int q = 0; q < 8; q++) acc[q] *= f;
                m = q0;
            }
            float w0 = __expf(q0 - m);
            s += w0;
            acc[0] += w0 * u0.x; acc[1] += w0 * u0.y; acc[2] += w0 * u0.z; acc[3] += w0 * u0.w;
            acc[4] += w0 * u1.x; acc[5] += w0 * u1.y; acc[6] += w0 * u1.z; acc[7] += w0 * u1.w;
        }
    }
    float inv = 1.0f / s;
    const float4* pb = (const float4*)(bias + off);
    float4 b0 = pb[0], b1 = pb[1];
    float4 o0, o1;
    o0.x = fmaxf(acc[0] * inv + b0.x, 0.f);
    o0.y = fmaxf(acc[1] * inv + b0.y, 0.f);
    o0.z = fmaxf(acc[2] * inv + b0.z, 0.f);
    o0.w = fmaxf(acc[3] * inv + b0.w, 0.f);
    o1.x = fmaxf(acc[4] * inv + b1.x, 0.f);
    o1.y = fmaxf(acc[5] * inv + b1.y, 0.f);
    o1.z = fmaxf(acc[6] * inv + b1.z, 0.f);
    o1.w = fmaxf(acc[7] * inv + b1.w, 0.f);
    float4* po = (float4*)(out + (size_t)n * HC + off);
    po[0] = o0; po[1] = o1;
}

// ---------------- fused GATv2 aggregation layer 2 + final linear ----------------
__global__ void __launch_bounds__(256) k_agg2(const int* __restrict__ rowptr,
                                              const int* __restrict__ csrc,
                                              const float* __restrict__ xl,
                                              const float* __restrict__ xr,
                                              const float* __restrict__ att,
                                              const float* __restrict__ bias,
                                              const float* __restrict__ Wlin,
                                              const float* __restrict__ blin,
                                              float* __restrict__ out) {
    int warp = (blockIdx.x * blockDim.x + threadIdx.x) >> 5;
    int lane = threadIdx.x & 31;
    if (warp >= NODES) return;
    int n = warp;
    int off = lane * 2;

    float2 r = *(const float2*)(xr + (size_t)n * OUTC + off);
    float2 a = *(const float2*)(att + off);

    float m = -INFINITY, s = 0.f;
    float acc0 = 0.f, acc1 = 0.f;

    int b = rowptr[n], e = rowptr[n + 1];
    for (int kb = b; kb < e; kb += 32) {
        int idx = kb + lane;
        int mysrc = (idx < e) ? csrc[idx] : 0;
        int cnt = min(32, e - kb);
        int j = 0;
        for (; j + 1 < cnt; j += 2) {
            int s0 = __shfl_sync(0xffffffffu, mysrc, j);
            int s1 = __shfl_sync(0xffffffffu, mysrc, j + 1);
            float2 v0 = *(const float2*)(xl + (size_t)s0 * OUTC + off);
            float2 v1 = *(const float2*)(xl + (size_t)s1 * OUTC + off);
            float q0 = lrelu(v0.x + r.x) * a.x + lrelu(v0.y + r.y) * a.y;
            float q1 = lrelu(v1.x + r.x) * a.x + lrelu(v1.y + r.y) * a.y;
#pragma unroll
            for (int d = 1; d < 32; d <<= 1) {
                q0 += __shfl_xor_sync(0xffffffffu, q0, d);
                q1 += __shfl_xor_sync(0xffffffffu, q1, d);
            }
            float pmax = fmaxf(q0, q1);
            if (pmax > m) {
                float f = __expf(m - pmax);
                s *= f; acc0 *= f; acc1 *= f;
                m = pmax;
            }
            float w0 = __expf(q0 - m), w1 = __expf(q1 - m);
            s += w0 + w1;
            acc0 += w0 * v0.x + w1 * v1.x;
            acc1 += w0 * v0.y + w1 * v1.y;
        }
        if (j < cnt) {
            int s0 = __shfl_sync(0xffffffffu, mysrc, j);
            float2 v0 = *(const float2*)(xl + (size_t)s0 * OUTC + off);
            float q0 = lrelu(v0.x + r.x) * a.x + lrelu(v0.y + r.y) * a.y;
#pragma unroll
            for (int d = 1; d < 32; d <<= 1)
                q0 += __shfl_xor_sync(0xffffffffu, q0, d);
            if (q0 > m) {
                float f = __expf(m - q0);
                s *= f; acc0 *= f; acc1 *= f;
                m = q0;
            }
            float w0 = __expf(q0 - m);
            s += w0;
            acc0 += w0 * v0.x;
            acc1 += w0 * v0.y;
        }
    }
    float inv = 1.0f / s;
    float2 bb = *(const float2*)(bias + off);
    float hx = fmaxf(acc0 * inv + bb.x, 0.f);
    float hy = fmaxf(acc1 * inv + bb.y, 0.f);

    float part[NC];
#pragma unroll
    for (int c = 0; c < NC; c++)
        part[c] = hx * Wlin[off * NC + c] + hy * Wlin[(off + 1) * NC + c];
#pragma unroll
    for (int d = 16; d >= 1; d >>= 1)
#pragma unroll
        for (int c = 0; c < NC; c++)
            part[c] += __shfl_xor_sync(0xffffffffu, part[c], d);
    if (lane == 0) {
#pragma unroll
        for (int c = 0; c < NC; c++)
            out[(size_t)n * NC + c] = part[c] + blin[c];
    }
}

// ---------------- launch ----------------
extern "C" void kernel_launch(void* const* d_in, const int* in_sizes, int n_in,
                              void* d_out, int out_size) {
    const float* x    = (const float*)d_in[0];
    const int*   ei   = (const int*)d_in[1];
    const float* Wl1  = (const float*)d_in[2];
    const float* Wr1  = (const float*)d_in[3];
    const float* att1 = (const float*)d_in[4];
    const float* b1   = (const float*)d_in[5];
    const float* Wl2  = (const float*)d_in[6];
    const float* Wr2  = (const float*)d_in[7];
    const float* att2 = (const float*)d_in[8];
    const float* b2   = (const float*)d_in[9];
    const float* Wlin = (const float*)d_in[10];
    const float* blin = (const float*)d_in[11];
    float* out = (float*)d_out;

    float *xl1, *xr1, *h1, *xl2, *xr2;
    __half *bt1h, *bt1l, *bt2h, *bt2l;
    int *rowptr, *csrc, *deg;
    cudaGetSymbolAddress((void**)&xl1, g_xl1);
    cudaGetSymbolAddress((void**)&xr1, g_xr1);
    cudaGetSymbolAddress((void**)&h1,  g_h1);
    cudaGetSymbolAddress((void**)&xl2, g_xl2);
    cudaGetSymbolAddress((void**)&xr2, g_xr2);
    cudaGetSymbolAddress((void**)&rowptr, g_rowptr);
    cudaGetSymbolAddress((void**)&csrc,   g_csrc);
    cudaGetSymbolAddress((void**)&deg,    g_deg);
    cudaGetSymbolAddress((void**)&bt1h, g_bt1_hi);
    cudaGetSymbolAddress((void**)&bt1l, g_bt1_lo);
    cudaGetSymbolAddress((void**)&bt2h, g_bt2_hi);
    cudaGetSymbolAddress((void**)&bt2l, g_bt2_lo);

    static cudaStream_t s2 = nullptr;
    static cudaEvent_t ev_fork = nullptr, ev_join = nullptr;
    if (!s2) {
        cudaStreamCreateWithFlags(&s2, cudaStreamNonBlocking);
        cudaEventCreateWithFlags(&ev_fork, cudaEventDisableTiming);
        cudaEventCreateWithFlags(&ev_join, cudaEventDisableTiming);
    }

    int mrows = (NODES + 127) / 128;   // 391

    // ---- fork: CSR build + layer-2 weight prep concurrent with prep1+gemm1 ----
    cudaEventRecord(ev_fork, 0);
    cudaStreamWaitEvent(s2, ev_fork, 0);

    cudaMemsetAsync(deg, 0, NODES * sizeof(int), s2);
    k_hist<<<(EDGES / 4 + 255) / 256, 256, 0, s2>>>(ei);
    k_scan_all<<<1, 1024, 0, s2>>>();
    k_fill<<<(EDGES / 4 + NODES + 255) / 256, 256, 0, s2>>>(ei);
    k_prep_B<<<(2 * 64 * 256 + 255) / 256, 256, 0, s2>>>(Wl2, Wr2, bt2h, bt2l, 64, 256);
    cudaEventRecord(ev_join, s2);

    k_prep_B<<<(2 * 256 * 256 + 255) / 256, 256>>>(Wl1, Wr1, bt1h, bt1l, 256, 256);
    gemm_mma<256><<<dim3(4, mrows), 256>>>(x, bt1h, bt1l, xl1, xr1, NODES);

    cudaStreamWaitEvent(0, ev_join, 0);

    k_agg1<<<(NODES + 7) / 8, 256>>>(rowptr, csrc, xl1, xr1, att1, b1, h1);
    gemm_mma<64><<<dim3(1, mrows), 256>>>(h1, bt2h, bt2l, xl2, xr2, NODES);
    k_agg2<<<(NODES + 7) / 8, 256>>>(rowptr, csrc, xl2, xr2, att2, b2, Wlin, blin, out);
}

// round 8
// speedup vs baseline: 7.9854x; 1.0473x over previous
#include <cuda_runtime.h>
#include <cuda_fp16.h>
#include <math.h>
#include <stdint.h>

// ---------------- problem constants ----------------
constexpr int NODES = 50000;
constexpr int EDGES = 800000;
constexpr int E2    = EDGES + NODES;   // 850000
constexpr int OUTC  = 64;
constexpr int HC    = 256;             // 4 heads * 64
constexpr int NC    = 10;
constexpr float NEG = 0.2f;
constexpr int NB_SCAN = (NODES + 1023) / 1024;  // 49

// ---------------- scratch (features in fp16) ----------------
__device__ __half g_xl1[(size_t)NODES * HC];
__device__ __half g_xr1[(size_t)NODES * HC];
__device__ __half g_h1 [(size_t)NODES * HC];
__device__ __half g_xl2[(size_t)NODES * OUTC];
__device__ __half g_xr2[(size_t)NODES * OUTC];
__device__ int   g_deg[NODES];
__device__ int   g_rowptr[NODES + 1];
__device__ int   g_cursor[NODES];
__device__ int   g_csrc[E2];
// transposed + fp16 hi/lo split weights
__device__ __half g_bt1_hi[512 * 256];
__device__ __half g_bt1_lo[512 * 256];
__device__ __half g_bt2_hi[128 * 256];
__device__ __half g_bt2_lo[128 * 256];

__device__ __forceinline__ float lrelu(float v) { return v > 0.f ? v : NEG * v; }

__device__ __forceinline__ uint32_t smem_u32(const void* p) {
    uint32_t a;
    asm("{ .reg .u64 t; cvta.to.shared.u64 t, %1; cvt.u32.u64 %0, t; }" : "=r"(a) : "l"(p));
    return a;
}

__device__ __forceinline__ void ldsm_x4(uint32_t* r, uint32_t addr) {
    asm volatile("ldmatrix.sync.aligned.m8n8.x4.shared.b16 {%0,%1,%2,%3}, [%4];"
                 : "=r"(r[0]), "=r"(r[1]), "=r"(r[2]), "=r"(r[3]) : "r"(addr));
}
__device__ __forceinline__ void ldsm_x2(uint32_t* r, uint32_t addr) {
    asm volatile("ldmatrix.sync.aligned.m8n8.x2.shared.b16 {%0,%1}, [%2];"
                 : "=r"(r[0]), "=r"(r[1]) : "r"(addr));
}
__device__ __forceinline__ void mma_fp16(float* c, const uint32_t* a, const uint32_t* b) {
    asm volatile("mma.sync.aligned.m16n8k16.row.col.f32.f16.f16.f32 "
                 "{%0,%1,%2,%3}, {%4,%5,%6,%7}, {%8,%9}, {%0,%1,%2,%3};"
                 : "+f"(c[0]), "+f"(c[1]), "+f"(c[2]), "+f"(c[3])
                 : "r"(a[0]), "r"(a[1]), "r"(a[2]), "r"(a[3]), "r"(b[0]), "r"(b[1]));
}

// unpack 8 consecutive halves (16B) into floats
struct F8 { float v[8]; };
__device__ __forceinline__ F8 ld_half8(const __half* p) {
    uint4 u = *(const uint4*)p;
    const __half2* h = (const __half2*)&u;
    F8 r;
    float2 f;
    f = __half22float2(h[0]); r.v[0] = f.x; r.v[1] = f.y;
    f = __half22float2(h[1]); r.v[2] = f.x; r.v[3] = f.y;
    f = __half22float2(h[2]); r.v[4] = f.x; r.v[5] = f.y;
    f = __half22float2(h[3]); r.v[6] = f.x; r.v[7] = f.y;
    return r;
}

// ---------------- weight prep: transpose + fp16 hi/lo split ----------------
__global__ void k_prep_B(const float* __restrict__ W0, const float* __restrict__ W1,
                         __half* __restrict__ bt_hi, __half* __restrict__ bt_lo,
                         int N, int K) {
    int t = blockIdx.x * blockDim.x + threadIdx.x;
    int total = 2 * N * K;
    if (t >= total) return;
    int mat = t / (N * K);
    int r = t - mat * (N * K);
    int n = r / K, k = r - n * K;
    const float* W = mat ? W1 : W0;
    float w = W[k * N + n];
    __half hi = __float2half_rn(w);
    bt_hi[t] = hi;
    bt_lo[t] = __float2half_rn(w - __half2float(hi));
}

// ---------------- fp16x2 tensor-core GEMM (mma.sync), fp16 output ----------------
// AT = float (layer 1 input x) or __half (layer 2 input h1).
template <int NBM, typename AT>
__global__ void __launch_bounds__(256, 1) gemm_mma(const AT* __restrict__ A,
                                                   const __half* __restrict__ Bh,
                                                   const __half* __restrict__ Bl,
                                                   __half* __restrict__ C0,
                                                   __half* __restrict__ C1,
                                                   int M) {
    constexpr int K = 256;
    constexpr int LDS = 40;
    constexpr bool AHALF = (sizeof(AT) == 2);
    __shared__ __half sAh[128 * LDS];
    __shared__ __half sBh[128 * LDS];
    __shared__ __half sBl[128 * LDS];

    int tid = threadIdx.x;
    int lane = tid & 31;
    int wid = tid >> 5;
    int warpM = wid >> 2;
    int warpN = wid & 3;
    int m0 = blockIdx.y * 128;
    int n0 = blockIdx.x * 128;

    uint32_t bAh = smem_u32(sAh);
    uint32_t bBh = smem_u32(sBh), bBl = smem_u32(sBl);

    float4 apf[4];     // float-A path
    uint4  apfh[2];    // half-A path
    int4 bhpf[2], blpf[2];

    auto gload = [&](int kb) {
        if constexpr (!AHALF) {
#pragma unroll
            for (int i = 0; i < 4; i++) {
                int u = tid + 256 * i;
                int row = u >> 3, c4 = u & 7;
                apf[i] = make_float4(0.f, 0.f, 0.f, 0.f);
                if (m0 + row < M)
                    apf[i] = *(const float4*)((const float*)A + (size_t)(m0 + row) * K + kb * 32 + c4 * 4);
            }
        } else {
#pragma unroll
            for (int i = 0; i < 2; i++) {
                int u = tid + 256 * i;
                int row = u >> 2, c8 = u & 3;
                apfh[i] = make_uint4(0, 0, 0, 0);
                if (m0 + row < M)
                    apfh[i] = *(const uint4*)((const __half*)A + (size_t)(m0 + row) * K + kb * 32 + c8 * 8);
            }
        }
#pragma unroll
        for (int i = 0; i < 2; i++) {
            int u = tid + 256 * i;
            int row = u >> 2, c = u & 3;
            size_t g = (size_t)(n0 + row) * K + kb * 32 + c * 8;
            bhpf[i] = *(const int4*)(Bh + g);
            blpf[i] = *(const int4*)(Bl + g);
        }
    };

    auto sstore = [&]() {
        if constexpr (!AHALF) {
#pragma unroll
            for (int i = 0; i < 4; i++) {
                int u = tid + 256 * i;
                int row = u >> 3, c4 = u & 7;
                float4 v = apf[i];
                __half2 h0, h1;
                h0.x = __float2half_rn(v.x);
                h0.y = __float2half_rn(v.y);
                h1.x = __float2half_rn(v.z);
                h1.y = __float2half_rn(v.w);
                int e = row * LDS + c4 * 4;
                *(__half2*)(sAh + e)     = h0;
                *(__half2*)(sAh + e + 2) = h1;
            }
        } else {
#pragma unroll
            for (int i = 0; i < 2; i++) {
                int u = tid + 256 * i;
                int row = u >> 2, c8 = u & 3;
                *(uint4*)(sAh + row * LDS + c8 * 8) = apfh[i];
            }
        }
#pragma unroll
        for (int i = 0; i < 2; i++) {
            int u = tid + 256 * i;
            int row = u >> 2, c = u & 3;
            int e = row * LDS + c * 8;
            *(int4*)(sBh + e) = bhpf[i];
            *(int4*)(sBl + e) = blpf[i];
        }
    };

    float acc[4][4][4];
#pragma unroll
    for (int f = 0; f < 4; f++)
#pragma unroll
        for (int g = 0; g < 4; g++)
#pragma unroll
            for (int q = 0; q < 4; q++) acc[f][g][q] = 0.f;

    int arow = warpM * 64 + (lane & 15);
    int akc  = (lane >> 4) << 3;
    int brow = warpN * 32 + (lane & 7);
    int bkc  = ((lane >> 3) & 1) << 3;

    gload(0);
    for (int kb = 0; kb < 8; kb++) {
        sstore();
        __syncthreads();
        if (kb < 7) gload(kb + 1);

#pragma unroll
        for (int kk = 0; kk < 2; kk++) {
            uint32_t aoff = (uint32_t)((arow * LDS + kk * 16 + akc) * 2);
            uint32_t boff = (uint32_t)((brow * LDS + kk * 16 + bkc) * 2);

            uint32_t ah[4][4], bh[4][2];
#pragma unroll
            for (int f = 0; f < 4; f++)
                ldsm_x4(ah[f], bAh + aoff + (uint32_t)(f * 16 * LDS * 2));
#pragma unroll
            for (int g = 0; g < 4; g++)
                ldsm_x2(bh[g], bBh + boff + (uint32_t)(g * 8 * LDS * 2));
#pragma unroll
            for (int f = 0; f < 4; f++)
#pragma unroll
                for (int g = 0; g < 4; g++)
                    mma_fp16(acc[f][g], ah[f], bh[g]);

            uint32_t bl[4][2];
#pragma unroll
            for (int g = 0; g < 4; g++)
                ldsm_x2(bl[g], bBl + boff + (uint32_t)(g * 8 * LDS * 2));
#pragma unroll
            for (int f = 0; f < 4; f++)
#pragma unroll
                for (int g = 0; g < 4; g++)
                    mma_fp16(acc[f][g], ah[f], bl[g]);
        }
        __syncthreads();
    }

#pragma unroll
    for (int f = 0; f < 4; f++) {
#pragma unroll
        for (int g = 0; g < 4; g++) {
            int row = m0 + warpM * 64 + f * 16 + (lane >> 2);
            int col = n0 + warpN * 32 + g * 8 + (lane & 3) * 2;
            int mat = col / NBM;
            int cc = col - mat * NBM;
            __half* Cp = mat ? C1 : C0;
            if (row < M) {
                __half2 v;
                v.x = __float2half_rn(acc[f][g][0]);
                v.y = __float2half_rn(acc[f][g][1]);
                *(__half2*)(Cp + (size_t)row * NBM + cc) = v;
            }
            if (row + 8 < M) {
                __half2 v;
                v.x = __float2half_rn(acc[f][g][2]);
                v.y = __float2half_rn(acc[f][g][3]);
                *(__half2*)(Cp + (size_t)(row + 8) * NBM + cc) = v;
            }
        }
    }
}

// ---------------- CSR build ----------------
__global__ void k_hist(const int* __restrict__ ei) {
    int t = blockIdx.x * blockDim.x + threadIdx.x;
    int e4 = t * 4;
    if (e4 + 3 < EDGES) {
        int4 d = *(const int4*)(ei + EDGES + e4);
        atomicAdd(&g_deg[d.x], 1);
        atomicAdd(&g_deg[d.y], 1);
        atomicAdd(&g_deg[d.z], 1);
        atomicAdd(&g_deg[d.w], 1);
    } else if (e4 < EDGES) {
        for (int e = e4; e < EDGES; e++) atomicAdd(&g_deg[ei[EDGES + e]], 1);
    }
}

__global__ void __launch_bounds__(1024) k_scan_all() {
    __shared__ int wsum[32];
    int tid = threadIdx.x;
    int lane = tid & 31, w = tid >> 5;
    int running = 0;
    for (int chunk = 0; chunk < NB_SCAN; chunk++) {
        int i = chunk * 1024 + tid;
        int v = (i < NODES) ? (g_deg[i] + 1) : 0;   // +1 = self loop
        int x = v;
#pragma unroll
        for (int d = 1; d < 32; d <<= 1) {
            int y = __shfl_up_sync(0xffffffffu, x, d);
            if (lane >= d) x += y;
        }
        if (lane == 31) wsum[w] = x;
        __syncthreads();
        if (w == 0) {
            int tsum = wsum[lane];
#pragma unroll
            for (int d = 1; d < 32; d <<= 1) {
                int y = __shfl_up_sync(0xffffffffu, tsum, d);
                if (lane >= d) tsum += y;
            }
            wsum[lane] = tsum;
        }
        __syncthreads();
        int incl = x + (w > 0 ? wsum[w - 1] : 0) + running;
        if (i < NODES) {
            g_rowptr[i] = incl - v;
            g_cursor[i] = incl - v;
            if (i == NODES - 1) g_rowptr[NODES] = incl;
        }
        running += wsum[31];
        __syncthreads();
    }
}

__global__ void k_fill(const int* __restrict__ ei) {
    int t = blockIdx.x * blockDim.x + threadIdx.x;
    constexpr int EQ = EDGES / 4;
    if (t < EQ) {
        int e4 = t * 4;
        int4 s = *(const int4*)(ei + e4);
        int4 d = *(const int4*)(ei + EDGES + e4);
        g_csrc[atomicAdd(&g_cursor[d.x], 1)] = s.x;
        g_csrc[atomicAdd(&g_cursor[d.y], 1)] = s.y;
        g_csrc[atomicAdd(&g_cursor[d.z], 1)] = s.z;
        g_csrc[atomicAdd(&g_cursor[d.w], 1)] = s.w;
    } else if (t < EQ + NODES) {
        int i = t - EQ;
        g_csrc[atomicAdd(&g_cursor[i], 1)] = i;
    }
}

// ---------------- fused GATv2 aggregation, layer 1 (H=4, C=64), fp16 features ----------------
__global__ void __launch_bounds__(256) k_agg1(const int* __restrict__ rowptr,
                                              const int* __restrict__ csrc,
                                              const __half* __restrict__ xl,
                                              const __half* __restrict__ xr,
                                              const float* __restrict__ att,
                                              const float* __restrict__ bias,
                                              __half* __restrict__ out) {
    int warp = (blockIdx.x * blockDim.x + threadIdx.x) >> 5;
    int lane = threadIdx.x & 31;
    if (warp >= NODES) return;
    int n = warp;
    int off = lane * 8;

    F8 rr = ld_half8(xr + (size_t)n * HC + off);
    const float4* pa = (const float4*)(att + off);
    float4 a0 = pa[0], a1 = pa[1];
    float aw[8] = {a0.x, a0.y, a0.z, a0.w, a1.x, a1.y, a1.z, a1.w};

    float m = -INFINITY, s = 0.f;
    float acc[8] = {0.f, 0.f, 0.f, 0.f, 0.f, 0.f, 0.f, 0.f};

    int b = rowptr[n], e = rowptr[n + 1];
    for (int kb = b; kb < e; kb += 32) {
        int idx = kb + lane;
        int mysrc = (idx < e) ? csrc[idx] : 0;
        int cnt = min(32, e - kb);
        int j = 0;
        for (; j + 1 < cnt; j += 2) {
            int s0 = __shfl_sync(0xffffffffu, mysrc, j);
            int s1 = __shfl_sync(0xffffffffu, mysrc, j + 1);
            F8 u = ld_half8(xl + (size_t)s0 * HC + off);
            F8 t = ld_half8(xl + (size_t)s1 * HC + off);
            float q0 = 0.f, q1 = 0.f;
#pragma unroll
            for (int q = 0; q < 8; q++) {
                q0 += lrelu(u.v[q] + rr.v[q]) * aw[q];
                q1 += lrelu(t.v[q] + rr.v[q]) * aw[q];
            }
            q0 += __shfl_xor_sync(0xffffffffu, q0, 1);
            q1 += __shfl_xor_sync(0xffffffffu, q1, 1);
            q0 += __shfl_xor_sync(0xffffffffu, q0, 2);
            q1 += __shfl_xor_sync(0xffffffffu, q1, 2);
            q0 += __shfl_xor_sync(0xffffffffu, q0, 4);
            q1 += __shfl_xor_sync(0xffffffffu, q1, 4);
            float pmax = fmaxf(q0, q1);
            if (pmax > m) {
                float f = __expf(m - pmax);
                s *= f;
#pragma unroll
                for (int q = 0; q < 8; q++) acc[q] *= f;
                m = pmax;
            }
            float w0 = __expf(q0 - m), w1 = __expf(q1 - m);
            s += w0 + w1;
#pragma unroll
            for (int q = 0; q < 8; q++)
                acc[q] += w0 * u.v[q] + w1 * t.v[q];
        }
        if (j < cnt) {
            int s0 = __shfl_sync(0xffffffffu, mysrc, j);
            F8 u = ld_half8(xl + (size_t)s0 * HC + off);
            float q0 = 0.f;
#pragma unroll
            for (int q = 0; q < 8; q++)
                q0 += lrelu(u.v[q] + rr.v[q]) * aw[q];
            q0 += __shfl_xor_sync(0xffffffffu, q0, 1);
            q0 += __shfl_xor_sync(0xffffffffu, q0, 2);
            q0 += __shfl_xor_sync(0xffffffffu, q0, 4);
            if (q0 > m) {
                float f = __expf(m - q0);
                s *= f;
#pragma unroll
                for (int q = 0; q < 8; q++) acc[q] *= f;
                m = q0;
            }
            float w0 = __expf(q0 - m);
            s += w0;
#pragma unroll
            for (int q = 0; q < 8; q++)
                acc[q] += w0 * u.v[q];
        }
    }
    float inv = 1.0f / s;
    const float4* pb = (const float4*)(bias + off);
    float4 b0 = pb[0], b1 = pb[1];
    float bw[8] = {b0.x, b0.y, b0.z, b0.w, b1.x, b1.y, b1.z, b1.w};
    __half hv[8];
#pragma unroll
    for (int q = 0; q < 8; q++)
        hv[q] = __float2half_rn(fmaxf(acc[q] * inv + bw[q], 0.f));
    *(uint4*)(out + (size_t)n * HC + off) = *(uint4*)hv;
}

// ---------------- fused GATv2 aggregation layer 2 + final linear, fp16 features ----------------
__global__ void __launch_bounds__(256) k_agg2(const int* __restrict__ rowptr,
                                              const int* __restrict__ csrc,
                                              const __half* __restrict__ xl,
                                              const __half* __restrict__ xr,
                                              const float* __restrict__ att,
                                              const float* __restrict__ bias,
                                              const float* __restrict__ Wlin,
                                              const float* __restrict__ blin,
                                              float* __restrict__ out) {
    int warp = (blockIdx.x * blockDim.x + threadIdx.x) >> 5;
    int lane = threadIdx.x & 31;
    if (warp >= NODES) return;
    int n = warp;
    int off = lane * 2;

    float2 r = __half22float2(*(const __half2*)(xr + (size_t)n * OUTC + off));
    float2 a = *(const float2*)(att + off);

    float m = -INFINITY, s = 0.f;
    float acc0 = 0.f, acc1 = 0.f;

    int b = rowptr[n], e = rowptr[n + 1];
    for (int kb = b; kb < e; kb += 32) {
        int idx = kb + lane;
        int mysrc = (idx < e) ? csrc[idx] : 0;
        int cnt = min(32, e - kb);
        int j = 0;
        for (; j + 1 < cnt; j += 2) {
            int s0 = __shfl_sync(0xffffffffu, mysrc, j);
            int s1 = __shfl_sync(0xffffffffu, mysrc, j + 1);
            float2 v0 = __half22float2(*(const __half2*)(xl + (size_t)s0 * OUTC + off));
            float2 v1 = __half22float2(*(const __half2*)(xl + (size_t)s1 * OUTC + off));
            float q0 = lrelu(v0.x + r.x) * a.x + lrelu(v0.y + r.y) * a.y;
            float q1 = lrelu(v1.x + r.x) * a.x + lrelu(v1.y + r.y) * a.y;
#pragma unroll
            for (int d = 1; d < 32; d <<= 1) {
                q0 += __shfl_xor_sync(0xffffffffu, q0, d);
                q1 += __shfl_xor_sync(0xffffffffu, q1, d);
            }
            float pmax = fmaxf(q0, q1);
            if (pmax > m) {
                float f = __expf(m - pmax);
                s *= f; acc0 *= f; acc1 *= f;
                m = pmax;
            }
            float w0 = __expf(q0 - m), w1 = __expf(q1 - m);
            s += w0 + w1;
            acc0 += w0 * v0.x + w1 * v1.x;
            acc1 += w0 * v0.y + w1 * v1.y;
        }
        if (j < cnt) {
            int s0 = __shfl_sync(0xffffffffu, mysrc, j);
            float2 v0 = __half22float2(*(const __half2*)(xl + (size_t)s0 * OUTC + off));
            float q0 = lrelu(v0.x + r.x) * a.x + lrelu(v0.y + r.y) * a.y;
#pragma unroll
            for (int d = 1; d < 32; d <<= 1)
                q0 += __shfl_xor_sync(0xffffffffu, q0, d);
            if (q0 > m) {
                float f = __expf(m - q0);
                s *= f; acc0 *= f; acc1 *= f;
                m = q0;
            }
            float w0 = __expf(q0 - m);
            s += w0;
            acc0 += w0 * v0.x;
            acc1 += w0 * v0.y;
        }
    }
    float inv = 1.0f / s;
    float2 bb = *(const float2*)(bias + off);
    float hx = fmaxf(acc0 * inv + bb.x, 0.f);
    float hy = fmaxf(acc1 * inv + bb.y, 0.f);

    float part[NC];
#pragma unroll
    for (int c = 0; c < NC; c++)
        part[c] = hx * Wlin[off * NC + c] + hy * Wlin[(off + 1) * NC + c];
#pragma unroll
    for (int d = 16; d >= 1; d >>= 1)
#pragma unroll
        for (int c = 0; c < NC; c++)
            part[c] += __shfl_xor_sync(0xffffffffu, part[c], d);
    if (lane == 0) {
#pragma unroll
        for (int c = 0; c < NC; c++)
            out[(size_t)n * NC + c] = part[c] + blin[c];
    }
}

// ---------------- launch ----------------
extern "C" void kernel_launch(void* const* d_in, const int* in_sizes, int n_in,
                              void* d_out, int out_size) {
    const float* x    = (const float*)d_in[0];
    const int*   ei   = (const int*)d_in[1];
    const float* Wl1  = (const float*)d_in[2];
    const float* Wr1  = (const float*)d_in[3];
    const float* att1 = (const float*)d_in[4];
    const float* b1   = (const float*)d_in[5];
    const float* Wl2  = (const float*)d_in[6];
    const float* Wr2  = (const float*)d_in[7];
    const float* att2 = (const float*)d_in[8];
    const float* b2   = (const float*)d_in[9];
    const float* Wlin = (const float*)d_in[10];
    const float* blin = (const float*)d_in[11];
    float* out = (float*)d_out;

    __half *xl1, *xr1, *h1, *xl2, *xr2;
    __half *bt1h, *bt1l, *bt2h, *bt2l;
    int *rowptr, *csrc, *deg;
    cudaGetSymbolAddress((void**)&xl1, g_xl1);
    cudaGetSymbolAddress((void**)&xr1, g_xr1);
    cudaGetSymbolAddress((void**)&h1,  g_h1);
    cudaGetSymbolAddress((void**)&xl2, g_xl2);
    cudaGetSymbolAddress((void**)&xr2, g_xr2);
    cudaGetSymbolAddress((void**)&rowptr, g_rowptr);
    cudaGetSymbolAddress((void**)&csrc,   g_csrc);
    cudaGetSymbolAddress((void**)&deg,    g_deg);
    cudaGetSymbolAddress((void**)&bt1h, g_bt1_hi);
    cudaGetSymbolAddress((void**)&bt1l, g_bt1_lo);
    cudaGetSymbolAddress((void**)&bt2h, g_bt2_hi);
    cudaGetSymbolAddress((void**)&bt2l, g_bt2_lo);

    static cudaStream_t s2 = nullptr;
    static cudaEvent_t ev_fork = nullptr, ev_join = nullptr;
    if (!s2) {
        cudaStreamCreateWithFlags(&s2, cudaStreamNonBlocking);
        cudaEventCreateWithFlags(&ev_fork, cudaEventDisableTiming);
        cudaEventCreateWithFlags(&ev_join, cudaEventDisableTiming);
    }

    int mrows = (NODES + 127) / 128;   // 391

    // ---- fork: CSR build + layer-2 weight prep concurrent with prep1+gemm1 ----
    cudaEventRecord(ev_fork, 0);
    cudaStreamWaitEvent(s2, ev_fork, 0);

    cudaMemsetAsync(deg, 0, NODES * sizeof(int), s2);
    k_hist<<<(EDGES / 4 + 255) / 256, 256, 0, s2>>>(ei);
    k_scan_all<<<1, 1024, 0, s2>>>();
    k_fill<<<(EDGES / 4 + NODES + 255) / 256, 256, 0, s2>>>(ei);
    k_prep_B<<<(2 * 64 * 256 + 255) / 256, 256, 0, s2>>>(Wl2, Wr2, bt2h, bt2l, 64, 256);
    cudaEventRecord(ev_join, s2);

    k_prep_B<<<(2 * 256 * 256 + 255) / 256, 256>>>(Wl1, Wr1, bt1h, bt1l, 256, 256);
    gemm_mma<256><<<dim3(4, mrows), 256>>>(x, bt1h, bt1l, xl1, xr1, NODES);

    cudaStreamWaitEvent(0, ev_join, 0);

    k_agg1<<<(NODES + 7) / 8, 256>>>(rowptr, csrc, xl1, xr1, att1, b1, h1);
    gemm_mma<64><<<dim3(1, mrows), 256>>>(h1, bt2h, bt2l, xl2, xr2, NODES);
    k_agg2<<<(NODES + 7) / 8, 256>>>(rowptr, csrc, xl2, xr2, att2, b2, Wlin, blin, out);
}